// round 13
// baseline (speedup 1.0000x reference)
#include <cuda_runtime.h>
#include <cuda_fp16.h>
#include <cstddef>

// Problem constants
#define BATCH 256
#define LSEQ  128
#define DD    6
#define FF    200
#define FA_   39
#define FB_   10
#define RR    2
#define MROWS (BATCH*LSEQ)          // 32768
#define MSLOT (MROWS*DD)            // 196608
#define KC    (FA_+FB_)             // 49
#define KPA   40                    // padded K for atom GEMM
#define KPC   56                    // padded K for nbr GEMM
#define KPF   200                   // F (16B-aligned rows: 400B)

// ---------------- scratch (device globals; no allocations allowed) ----------
__device__ __half h_cur   [(size_t)MROWS*FF];
__device__ __half h_cur2  [(size_t)MROWS*FF];
__device__ __half h_ctxpre[(size_t)MROWS*FF];
__device__ __half h_ctx   [(size_t)MROWS*FF];
__device__ float  g_s     [MROWS];
__device__ __half h_nbr   [(size_t)MSLOT*FF];
__device__ __half h_acat  [(size_t)MSLOT*KPC];
__device__ __half h_atom  [(size_t)MROWS*KPA];
__device__ __half h_atomW [FF*KPA];
__device__ __half h_nbrW  [FF*KPC];
__device__ __half h_attW  [RR*FF*FF];
__device__ __half h_Wih   [(size_t)RR*3*FF*FF];
__device__ __half h_Whh   [(size_t)RR*3*FF*FF];

// ---------------- PTX helpers ------------------------------------------------
__device__ __forceinline__ void mma_f16(float* c, const unsigned* a, const unsigned* b) {
    asm volatile(
        "mma.sync.aligned.m16n8k16.row.col.f32.f16.f16.f32 "
        "{%0,%1,%2,%3}, {%4,%5,%6,%7}, {%8,%9}, {%0,%1,%2,%3};"
        : "+f"(c[0]), "+f"(c[1]), "+f"(c[2]), "+f"(c[3])
        : "r"(a[0]), "r"(a[1]), "r"(a[2]), "r"(a[3]), "r"(b[0]), "r"(b[1]));
}

__device__ __forceinline__ void ldsm4(unsigned& r0, unsigned& r1, unsigned& r2, unsigned& r3,
                                      const void* p) {
    unsigned addr = (unsigned)__cvta_generic_to_shared(p);
    asm volatile("ldmatrix.sync.aligned.m8n8.x4.shared.b16 {%0,%1,%2,%3}, [%4];"
                 : "=r"(r0), "=r"(r1), "=r"(r2), "=r"(r3) : "r"(addr));
}

__device__ __forceinline__ void cpa16h(__half* dst, const __half* src, int bytes) {
    unsigned d = (unsigned)__cvta_generic_to_shared(dst);
    asm volatile("cp.async.cg.shared.global [%0], [%1], 16, %2;\n"
                 :: "r"(d), "l"(src), "r"(bytes));
}
__device__ __forceinline__ void cp_commit() { asm volatile("cp.async.commit_group;\n"); }
template<int N>
__device__ __forceinline__ void cp_wait() {
    asm volatile("cp.async.wait_group %0;\n" :: "n"(N));
}

// =================== fp16 tensor-core GEMM (BK=32) ===========================
//   C[M,N] = act(A[M,Kp] @ W[N,Kp]^T + bias[N]*rowscale[M]), C stored __half.
//   ACT: 0=none, 1=leaky_relu(0.01), 2=elu.
// BM=BN=128, BK=32, 3 stages (48KB exactly); 8 warps (2M x 4N), warp 64x32.
// Smem row = 32 halves (4 x 16B chunks); chunk c of row m at c ^ ((m>>1)&3).
#define SBM 128
#define SBN 128
#define SBK 32
#define GSTG 3
#define EPS 136      // epilogue smem row stride in halves

template<int ACT>
__global__ void __launch_bounds__(256, 2)
gemm_h(const __half* __restrict__ A, const __half* __restrict__ W,
       const float* __restrict__ bias, const float* __restrict__ rowscale,
       __half* __restrict__ C, int M, int N, int Kp)
{
    // pipeline: 3*(128+128)*32 halves = 49152B; epilogue reuse: 128*136*2=34816B
    __shared__ __align__(16) __half smem_all[GSTG * (SBM + SBN) * SBK];
#define AS(S) ((__half(*)[SBK])(smem_all + (size_t)(S) * (SBM + SBN) * SBK))
#define BS(S) ((__half(*)[SBK])(smem_all + ((size_t)(S) * (SBM + SBN) + SBM) * SBK))

    const int tid   = threadIdx.x;
    const int lane  = tid & 31;
    const int warp  = tid >> 5;
    const int warpM = warp & 1;
    const int warpN = warp >> 1;
    const int mBase = blockIdx.y * SBM;
    const int nBase = blockIdx.x * SBN;
    const int nk    = (Kp + SBK - 1) / SBK;
    const int r0 = lane >> 2;
    const int c0 = lane & 3;
    const int lrowA = ((lane >> 3) & 1) * 8 + (lane & 7);
    const int lchA  = lane >> 4;
    const int lrowB = (lane >> 4) * 8 + (lane & 7);
    const int lchB  = (lane >> 3) & 1;

    float acc[4][4][4];
    #pragma unroll
    for (int mt = 0; mt < 4; mt++)
        #pragma unroll
        for (int nt = 0; nt < 4; nt++)
            #pragma unroll
            for (int i = 0; i < 4; i++) acc[mt][nt][i] = 0.f;

#define LOAD(S, KT)                                                            \
    {                                                                          \
        int kbase = (KT) * SBK;                                                \
        _Pragma("unroll")                                                      \
        for (int it = 0; it < 2; it++) {                                       \
            int e = tid + it * 256;                                            \
            int m = e >> 2, c = e & 3;                                         \
            int k0 = kbase + c * 8;                                            \
            int bytes = (k0 < Kp) ? 16 : 0;                                    \
            const __half* src = A + (size_t)(mBase + m) * Kp + (bytes ? k0 : 0);\
            cpa16h(&AS(S)[m][(c ^ ((m >> 1) & 3)) * 8], src, bytes);           \
        }                                                                      \
        _Pragma("unroll")                                                      \
        for (int it = 0; it < 2; it++) {                                       \
            int e = tid + it * 256;                                            \
            int n = e >> 2, c = e & 3;                                         \
            int gn = nBase + n, k0 = kbase + c * 8;                            \
            int bytes = (gn < N && k0 < Kp) ? 16 : 0;                          \
            const __half* src = W + (size_t)(gn < N ? gn : 0) * Kp             \
                                  + (bytes ? k0 : 0);                          \
            cpa16h(&BS(S)[n][(c ^ ((n >> 1) & 3)) * 8], src, bytes);           \
        }                                                                      \
        cp_commit();                                                           \
    }

    #pragma unroll
    for (int s = 0; s < GSTG - 1; s++) {
        if (s < nk) { LOAD(s, s); } else { cp_commit(); }
    }

    for (int kt = 0; kt < nk; kt++) {
        const int st = kt % GSTG;
        cp_wait<GSTG - 2>();
        __syncthreads();

        int ktn = kt + GSTG - 1;
        if (ktn < nk) { LOAD(ktn % GSTG, ktn); } else { cp_commit(); }

        const __half (*as)[SBK] = AS(st);
        const __half (*bs)[SBK] = BS(st);

        #pragma unroll
        for (int hk = 0; hk < 2; hk++) {
            unsigned a[4][4];
            #pragma unroll
            for (int mt = 0; mt < 4; mt++) {
                int row = warpM * 64 + mt * 16 + lrowA;
                int ch = (hk * 2 + lchA) ^ ((row >> 1) & 3);
                ldsm4(a[mt][0], a[mt][1], a[mt][2], a[mt][3], &as[row][ch * 8]);
            }
            unsigned b[4][2];
            #pragma unroll
            for (int p = 0; p < 2; p++) {
                int row = warpN * 32 + p * 16 + lrowB;
                int ch = (hk * 2 + lchB) ^ ((row >> 1) & 3);
                unsigned t0, t1, t2, t3;
                ldsm4(t0, t1, t2, t3, &bs[row][ch * 8]);
                b[2 * p][0]     = t0; b[2 * p][1]     = t1;
                b[2 * p + 1][0] = t2; b[2 * p + 1][1] = t3;
            }
            #pragma unroll
            for (int mt = 0; mt < 4; mt++)
                #pragma unroll
                for (int nt = 0; nt < 4; nt++)
                    mma_f16(acc[mt][nt], a[mt], b[nt]);
        }
    }

    // -------- epilogue: bias+act -> padded smem -> coalesced STG.128 --------
    __syncthreads();
    __half* ep = smem_all;
    #pragma unroll
    for (int mt = 0; mt < 4; mt++) {
        int lr = warpM * 64 + mt * 16 + r0;
        int grow0 = mBase + lr;
        float s0 = rowscale ? rowscale[grow0]     : 1.f;
        float s1 = rowscale ? rowscale[grow0 + 8] : 1.f;
        #pragma unroll
        for (int nt = 0; nt < 4; nt++) {
            int lc  = warpN * 32 + nt * 8 + c0 * 2;
            int col = nBase + lc;
            float b0 = (col < N)     ? bias[col]     : 0.f;
            float b1 = (col + 1 < N) ? bias[col + 1] : 0.f;
            float v00 = acc[mt][nt][0] + b0 * s0;
            float v01 = acc[mt][nt][1] + b1 * s0;
            float v10 = acc[mt][nt][2] + b0 * s1;
            float v11 = acc[mt][nt][3] + b1 * s1;
            if (ACT == 1) {
                v00 = (v00 > 0.f) ? v00 : 0.01f * v00;
                v01 = (v01 > 0.f) ? v01 : 0.01f * v01;
                v10 = (v10 > 0.f) ? v10 : 0.01f * v10;
                v11 = (v11 > 0.f) ? v11 : 0.01f * v11;
            } else if (ACT == 2) {
                v00 = (v00 > 0.f) ? v00 : expm1f(v00);
                v01 = (v01 > 0.f) ? v01 : expm1f(v01);
                v10 = (v10 > 0.f) ? v10 : expm1f(v10);
                v11 = (v11 > 0.f) ? v11 : expm1f(v11);
            }
            *(half2*)&ep[(lr    ) * EPS + lc] = __floats2half2_rn(v00, v01);
            *(half2*)&ep[(lr + 8) * EPS + lc] = __floats2half2_rn(v10, v11);
        }
    }
    __syncthreads();
    for (int it = tid; it < SBM * 16; it += 256) {
        int r  = it >> 4, ck = it & 15;
        int gc = nBase + ck * 8;
        if (gc < N) {
            *(uint4*)&C[(size_t)(mBase + r) * N + gc] = *(const uint4*)&ep[r * EPS + ck * 8];
        }
    }
#undef LOAD
#undef AS
#undef BS
}

// =================== fused gi+gh GEMM + GRU epilogue (j-tile 32) =============
// Block: 128 rows x 32 F-cols; 6 gate tiles -> B = 192 rows. 512 threads,
// 16 warps: warpM 0..7 (16 rows), warpN 0..1 (0: ctx@Wih, 1: cur@Whh).
// Warp computes 16 rows x 96 gate-cols = 12 ntiles. K=200, BK=16, 3 stages.
#define GBM 128
#define GJ  32
#define GBR (3*GJ*2)      // 192 B rows
#define GROWS (GBM + GBM + GBR)  // 448
#define FSTG 3

__global__ void __launch_bounds__(512, 1)
gru_fused(const __half* __restrict__ ctx, const __half* __restrict__ cur,
          const __half* __restrict__ Wih, const __half* __restrict__ Whh,
          const float* __restrict__ bih, const float* __restrict__ bhh,
          __half* __restrict__ curout, float* __restrict__ outf, int finalr)
{
    __shared__ __align__(16) __half smraw[FSTG * GROWS * 16];  // 43008 B

    const int tid   = threadIdx.x;
    const int lane  = tid & 31;
    const int warp  = tid >> 5;
    const int warpM = warp & 7;         // 16 rows each
    const int warpN = warp >> 3;        // 0..1
    const int mBase = blockIdx.y * GBM;
    const int jBase = blockIdx.x * GJ;
    const int nk    = (KPF + 15) / 16;  // 13
    const int r0 = lane >> 2;
    const int c0 = lane & 3;
    const int lrowA = ((lane >> 3) & 1) * 8 + (lane & 7);
    const int lchA  = lane >> 4;
    const int lrowB = (lane >> 4) * 8 + (lane & 7);
    const int lchB  = (lane >> 3) & 1;

    float acc[12][4];
    #pragma unroll
    for (int nt = 0; nt < 12; nt++)
        #pragma unroll
        for (int i = 0; i < 4; i++) acc[nt][i] = 0.f;

#define SCTX(S) ((__half(*)[16])(smraw + (size_t)(S) * GROWS * 16))
#define SCUR(S) ((__half(*)[16])(smraw + ((size_t)(S) * GROWS + GBM) * 16))
#define SB(S)   ((__half(*)[16])(smraw + ((size_t)(S) * GROWS + 2*GBM) * 16))

#define FLOAD(S, KT)                                                           \
    {                                                                          \
        int kbase = (KT) * 16;                                                 \
        {                                                                      \
            int m = (tid & 255) >> 1, c = tid & 1;                             \
            int k0 = kbase + c * 8;                                            \
            int bytes = (k0 < KPF) ? 16 : 0;                                   \
            size_t off = (size_t)(mBase + m) * KPF + (bytes ? k0 : 0);         \
            int sc = (c ^ ((m >> 2) & 1)) * 8;                                 \
            if (tid < 256) cpa16h(&SCTX(S)[m][sc], ctx + off, bytes);          \
            else           cpa16h(&SCUR(S)[m][sc], cur + off, bytes);          \
        }                                                                      \
        if (tid < 2 * GBR) {                                                   \
            int rn = tid >> 1, c = tid & 1;                                    \
            int gate = rn >> 5;                                                \
            int jj = jBase + (rn & 31);                                        \
            int k0 = kbase + c * 8;                                            \
            int bytes = (jj < FF && k0 < KPF) ? 16 : 0;                        \
            int jjc = (jj < FF) ? jj : 0;                                      \
            const __half* src = (gate < 3)                                     \
                ? Wih + ((size_t)gate * FF + jjc) * KPF                        \
                : Whh + ((size_t)(gate - 3) * FF + jjc) * KPF;                 \
            cpa16h(&SB(S)[rn][(c ^ ((rn >> 2) & 1)) * 8],                      \
                   src + (bytes ? k0 : 0), bytes);                             \
        }                                                                      \
        cp_commit();                                                           \
    }

    #pragma unroll
    for (int s = 0; s < FSTG - 1; s++) { FLOAD(s, s); }

    for (int kt = 0; kt < nk; kt++) {
        const int st = kt % FSTG;
        cp_wait<FSTG - 2>();
        __syncthreads();

        int ktn = kt + FSTG - 1;
        if (ktn < nk) { FLOAD(ktn % FSTG, ktn); } else { cp_commit(); }

        const __half (*amat)[16] = warpN ? SCUR(st) : SCTX(st);
        const __half (*bs)[16]   = SB(st);

        unsigned a[4];
        {
            int row = warpM * 16 + lrowA;
            int swc = lchA ^ ((row >> 2) & 1);
            ldsm4(a[0], a[1], a[2], a[3], &amat[row][swc * 8]);
        }
        unsigned b[12][2];
        #pragma unroll
        for (int p = 0; p < 6; p++) {
            int row = warpN * 96 + p * 16 + lrowB;
            int swc = lchB ^ ((row >> 2) & 1);
            unsigned t0, t1, t2, t3;
            ldsm4(t0, t1, t2, t3, &bs[row][swc * 8]);
            b[2 * p][0]     = t0; b[2 * p][1]     = t1;
            b[2 * p + 1][0] = t2; b[2 * p + 1][1] = t3;
        }
        #pragma unroll
        for (int nt = 0; nt < 12; nt++)
            mma_f16(acc[nt], a, b[nt]);
    }

    // -------- two-wave exchange + GRU epilogue --------
    // ntile nt = gate*4 + jt, gate in {0:r,1:z,2:n}, jt = j-octet 0..3.
    __syncthreads();
    float* ex = (float*)smraw;          // stride 25: 256*25*4 = 25600 B
    #pragma unroll
    for (int w = 0; w < 2; w++) {
        if (w) __syncthreads();
        if (warpN == 1) {
            int base = (warpM * 32 + lane) * 25;
            #pragma unroll
            for (int g = 0; g < 3; g++)
                #pragma unroll
                for (int jt2 = 0; jt2 < 2; jt2++) {
                    int nt = g * 4 + 2 * w + jt2;
                    #pragma unroll
                    for (int i = 0; i < 4; i++)
                        ex[base + (g * 2 + jt2) * 4 + i] = acc[nt][i];
                }
        }
        __syncthreads();
        if (warpN == 0) {
            int base = (warpM * 32 + lane) * 25;
            #pragma unroll
            for (int jt2 = 0; jt2 < 2; jt2++) {
                int jt = 2 * w + jt2;
                int j0 = jBase + jt * 8 + c0 * 2;
                if (j0 < FF) {
                    #pragma unroll
                    for (int hf = 0; hf < 2; hf++) {
                        int row = mBase + warpM * 16 + r0 + hf * 8;
                        half2 cpair = *(const half2*)&cur[(size_t)row * FF + j0];
                        float hv[2];
                        #pragma unroll
                        for (int q = 0; q < 2; q++) {
                            int i = hf * 2 + q;
                            int j = j0 + q;
                            float ir  = acc[0 * 4 + jt][i] + bih[j];
                            float iz  = acc[1 * 4 + jt][i] + bih[FF + j];
                            float inn = acc[2 * 4 + jt][i] + bih[2 * FF + j];
                            float hr  = ex[base + (0 * 2 + jt2) * 4 + i] + bhh[j];
                            float hz  = ex[base + (1 * 2 + jt2) * 4 + i] + bhh[FF + j];
                            float hn  = ex[base + (2 * 2 + jt2) * 4 + i] + bhh[2 * FF + j];
                            float r = 1.f / (1.f + expf(-(ir + hr)));
                            float z = 1.f / (1.f + expf(-(iz + hz)));
                            float n = tanhf(inn + r * hn);
                            float c = q ? __half2float(__high2half(cpair))
                                        : __half2float(__low2half(cpair));
                            float h = (1.f - z) * n + z * c;
                            hv[q] = (h > 0.f) ? h : 0.f;
                        }
                        if (finalr) {
                            float2 t; t.x = hv[0]; t.y = hv[1];
                            *(float2*)&outf[(size_t)row * FF + j0] = t;
                        } else {
                            *(half2*)&curout[(size_t)row * FF + j0] =
                                __floats2half2_rn(hv[0], hv[1]);
                        }
                    }
                }
            }
        }
    }
#undef FLOAD
#undef SCTX
#undef SCUR
#undef SB
}

// ---------------- single fused fp32->fp16 (padded) conversion ---------------
#define W2H_C0 (MROWS*KPA)
#define W2H_C1 (W2H_C0 + FF*KPA)
#define W2H_C2 (W2H_C1 + FF*KPC)
#define W2H_C3 (W2H_C2 + RR*FF*FF)
#define W2H_C4 (W2H_C3 + RR*3*FF*FF)
#define W2H_C5 (W2H_C4 + RR*3*FF*FF)

__global__ void w2h_all(const float* __restrict__ atom_list,
                        const float* __restrict__ atom_W,
                        const float* __restrict__ nbr_W,
                        const float* __restrict__ attend_W,
                        const float* __restrict__ gWih,
                        const float* __restrict__ gWhh,
                        __half* __restrict__ ha,  __half* __restrict__ haw,
                        __half* __restrict__ hnw, __half* __restrict__ hat,
                        __half* __restrict__ hwi, __half* __restrict__ hwh)
{
    int i = blockIdx.x * blockDim.x + threadIdx.x;
    if (i < W2H_C0) {
        int n = i / KPA, k = i - n * KPA;
        ha[i] = (k < FA_) ? __float2half_rn(atom_list[(size_t)n * FA_ + k]) : __half(0.f);
    } else if (i < W2H_C1) {
        int j = i - W2H_C0; int n = j / KPA, k = j - n * KPA;
        haw[j] = (k < FA_) ? __float2half_rn(atom_W[(size_t)n * FA_ + k]) : __half(0.f);
    } else if (i < W2H_C2) {
        int j = i - W2H_C1; int n = j / KPC, k = j - n * KPC;
        hnw[j] = (k < KC) ? __float2half_rn(nbr_W[(size_t)n * KC + k]) : __half(0.f);
    } else if (i < W2H_C3) {
        int j = i - W2H_C2; hat[j] = __float2half_rn(attend_W[j]);
    } else if (i < W2H_C4) {
        int j = i - W2H_C3; hwi[j] = __float2half_rn(gWih[j]);
    } else if (i < W2H_C5) {
        int j = i - W2H_C4; hwh[j] = __float2half_rn(gWhh[j]);
    }
}

// ---------------- gather concat(atom_nbr, bond_nbr) -> half [MSLOT, KPC] ----
__global__ void gather_acat_kernel(const float* __restrict__ atom_list,
                                   const float* __restrict__ bond_list,
                                   const int*   __restrict__ adeg,
                                   const int*   __restrict__ bdeg,
                                   __half* __restrict__ acat)
{
    int e = blockIdx.x * blockDim.x + threadIdx.x;
    if (e >= MSLOT * KPC) return;
    int slot = e / KPC;
    int k    = e - slot * KPC;
    int b    = slot / (LSEQ * DD);
    float v = 0.f;
    if (k < FA_) {
        int a = adeg[slot];
        v = atom_list[((size_t)b * LSEQ + a) * FA_ + k];
    } else if (k < KC) {
        int bb = bdeg[slot];
        v = bond_list[((size_t)b * LSEQ + bb) * FB_ + (k - FA_)];
    }
    acat[e] = __float2half_rn(v);
}

// ---------------- attention: warp per row ------------------------------------
__global__ void __launch_bounds__(256)
attention_kernel(const __half* __restrict__ cur,
                 const __half* __restrict__ nbrfeat,
                 const int*    __restrict__ adeg,
                 const float*  __restrict__ alignW,
                 const float*  __restrict__ alignB,
                 __half* __restrict__ ctxpre,
                 float*  __restrict__ srow,
                 int first)
{
    int gw   = (blockIdx.x * blockDim.x + threadIdx.x) >> 5;
    int lane = threadIdx.x & 31;
    if (gw >= MROWS) return;
    const int r = gw;
    const int b = r >> 7;
    const float ab = alignB[0];

    float cv[7], a0[7], a1[7];
    #pragma unroll
    for (int i = 0; i < 7; i++) {
        int idx = lane + 32 * i;
        bool ok = idx < FF;
        cv[i] = ok ? __half2float(cur[(size_t)r * FF + idx]) : 0.f;
        a0[i] = ok ? alignW[idx]      : 0.f;
        a1[i] = ok ? alignW[FF + idx] : 0.f;
    }
    float qd = 0.f;
    #pragma unroll
    for (int i = 0; i < 7; i++) qd += cv[i] * a0[i];
    #pragma unroll
    for (int o = 16; o > 0; o >>= 1) qd += __shfl_xor_sync(0xffffffffu, qd, o);

    float nv[DD][7];
    float score[DD];
    int   nai[DD];

    #pragma unroll
    for (int d = 0; d < DD; d++) {
        int na = adeg[r * DD + d];
        nai[d] = na;
        const __half* np = first ? (nbrfeat + ((size_t)r * DD + d) * FF)
                                 : (cur + ((size_t)(b * LSEQ + na)) * FF);
        float nd = 0.f;
        #pragma unroll
        for (int i = 0; i < 7; i++) {
            int idx = lane + 32 * i;
            float v = (idx < FF) ? __half2float(np[idx]) : 0.f;
            nv[d][i] = v;
            nd += v * a1[i];
        }
        #pragma unroll
        for (int o = 16; o > 0; o >>= 1) nd += __shfl_xor_sync(0xffffffffu, nd, o);
        float sc = qd + nd + ab;
        sc = (sc > 0.f) ? sc : 0.01f * sc;
        if (na == LSEQ - 1) sc = sc - 9e8f;
        score[d] = sc;
    }

    float mx = score[0];
    #pragma unroll
    for (int d = 1; d < DD; d++) mx = fmaxf(mx, score[d]);
    float e[DD], den = 0.f;
    #pragma unroll
    for (int d = 0; d < DD; d++) { e[d] = expf(score[d] - mx); den += e[d]; }
    float inv = 1.f / den;
    float s = 0.f;
    #pragma unroll
    for (int d = 0; d < DD; d++) {
        float a = e[d] * inv;
        if (nai[d] == LSEQ - 1) a = 0.f;
        e[d] = a;
        s += a;
    }

    #pragma unroll
    for (int i = 0; i < 7; i++) {
        int idx = lane + 32 * i;
        if (idx < FF) {
            float v = 0.f;
            #pragma unroll
            for (int d = 0; d < DD; d++) v += e[d] * nv[d][i];
            ctxpre[(size_t)r * FF + idx] = __float2half_rn(v);
        }
    }
    if (lane == 0) srow[r] = s;
}

// ---------------- launch ------------------------------------------------------
static inline int ceil_div(int a, int b) { return (a + b - 1) / b; }

extern "C" void kernel_launch(void* const* d_in, const int* in_sizes, int n_in,
                              void* d_out, int out_size)
{
    const float* atom_list = (const float*)d_in[0];
    const float* bond_list = (const float*)d_in[1];
    const int*   adeg      = (const int*)  d_in[2];
    const int*   bdeg      = (const int*)  d_in[3];
    const float* atom_W    = (const float*)d_in[4];
    const float* atom_b    = (const float*)d_in[5];
    const float* nbr_W     = (const float*)d_in[6];
    const float* nbr_b     = (const float*)d_in[7];
    const float* align_W   = (const float*)d_in[8];
    const float* align_b   = (const float*)d_in[9];
    const float* attend_W  = (const float*)d_in[10];
    const float* attend_b  = (const float*)d_in[11];
    const float* gWih      = (const float*)d_in[12];
    const float* gWhh      = (const float*)d_in[13];
    const float* gbih      = (const float*)d_in[14];
    const float* gbhh      = (const float*)d_in[15];
    float* out = (float*)d_out;

    __half *cur, *cur2, *ctxpre, *ctx, *nbr, *acat, *atomh;
    __half *atomWh, *nbrWh, *attWh, *Wihh, *Whhh;
    float *s;
    cudaGetSymbolAddress((void**)&cur,    h_cur);
    cudaGetSymbolAddress((void**)&cur2,   h_cur2);
    cudaGetSymbolAddress((void**)&ctxpre, h_ctxpre);
    cudaGetSymbolAddress((void**)&ctx,    h_ctx);
    cudaGetSymbolAddress((void**)&s,      g_s);
    cudaGetSymbolAddress((void**)&nbr,    h_nbr);
    cudaGetSymbolAddress((void**)&acat,   h_acat);
    cudaGetSymbolAddress((void**)&atomh,  h_atom);
    cudaGetSymbolAddress((void**)&atomWh, h_atomW);
    cudaGetSymbolAddress((void**)&nbrWh,  h_nbrW);
    cudaGetSymbolAddress((void**)&attWh,  h_attW);
    cudaGetSymbolAddress((void**)&Wihh,   h_Wih);
    cudaGetSymbolAddress((void**)&Whhh,   h_Whh);

    // 1. fused fp16 conversion of all GEMM operands
    w2h_all<<<ceil_div(W2H_C5, 256), 256>>>(
        atom_list, atom_W, nbr_W, attend_W, gWih, gWhh,
        atomh, atomWh, nbrWh, attWh, Wihh, Whhh);

    // 2. cur = leaky(atom_list @ atom_W^T + atom_b)
    gemm_h<1><<<dim3(ceil_div(FF, SBN), MROWS / SBM), 256>>>(
        atomh, atomWh, atom_b, nullptr, cur, MROWS, FF, KPA);

    // 3. gather concat inputs
    gather_acat_kernel<<<ceil_div(MSLOT * KPC, 256), 256>>>(
        atom_list, bond_list, adeg, bdeg, acat);

    // 4. nbrfeat = leaky(acat @ nbr_W^T + nbr_b)
    gemm_h<1><<<dim3(ceil_div(FF, SBN), MSLOT / SBM), 256>>>(
        acat, nbrWh, nbr_b, nullptr, nbr, MSLOT, FF, KPC);

    __half* curbuf[2] = { cur, cur2 };
    for (int d = 0; d < RR; d++) {
        __half* curin   = curbuf[d & 1];
        __half* curoutp = curbuf[(d + 1) & 1];

        attention_kernel<<<MROWS / 8, 256>>>(
            curin, nbr, adeg,
            align_W + (size_t)d * 2 * FF, align_b + d,
            ctxpre, s, (d == 0) ? 1 : 0);

        // launch #6 (round 0) -> captured by ncu (-s 5 -c 1)
        gemm_h<2><<<dim3(ceil_div(FF, SBN), MROWS / SBM), 256>>>(
            ctxpre, attWh + (size_t)d * FF * FF, attend_b + (size_t)d * FF, s,
            ctx, MROWS, FF, KPF);

        gru_fused<<<dim3(ceil_div(FF, GJ), MROWS / GBM), 512>>>(
            ctx, curin,
            Wihh + (size_t)d * 3 * FF * FF, Whhh + (size_t)d * 3 * FF * FF,
            gbih + (size_t)d * 3 * FF, gbhh + (size_t)d * 3 * FF,
            curoutp, out, (d == RR - 1) ? 1 : 0);
    }
}

// round 15
// speedup vs baseline: 1.0475x; 1.0475x over previous
#include <cuda_runtime.h>
#include <cuda_fp16.h>
#include <cstddef>

// Problem constants
#define BATCH 256
#define LSEQ  128
#define DD    6
#define FF    200
#define FA_   39
#define FB_   10
#define RR    2
#define MROWS (BATCH*LSEQ)          // 32768
#define MSLOT (MROWS*DD)            // 196608
#define KC    (FA_+FB_)             // 49
#define KPA   40                    // padded K for atom GEMM
#define KPC   56                    // padded K for nbr GEMM
#define KPF   200                   // F (16B-aligned rows: 400B)

// ---------------- scratch (device globals; no allocations allowed) ----------
__device__ __half h_cur   [(size_t)MROWS*FF];
__device__ __half h_cur2  [(size_t)MROWS*FF];
__device__ __half h_ctxpre[(size_t)MROWS*FF];
__device__ __half h_ctx   [(size_t)MROWS*FF];
__device__ float  g_s     [MROWS];
__device__ __half h_nbr   [(size_t)MSLOT*FF];
__device__ __half h_acat  [(size_t)MSLOT*KPC];
__device__ __half h_atom  [(size_t)MROWS*KPA];
__device__ __half h_atomW [FF*KPA];
__device__ __half h_nbrW  [FF*KPC];
__device__ __half h_attW  [RR*FF*FF];
__device__ __half h_Wih   [(size_t)RR*3*FF*FF];
__device__ __half h_Whh   [(size_t)RR*3*FF*FF];

// ---------------- PTX helpers ------------------------------------------------
__device__ __forceinline__ void mma_f16(float* c, const unsigned* a, const unsigned* b) {
    asm volatile(
        "mma.sync.aligned.m16n8k16.row.col.f32.f16.f16.f32 "
        "{%0,%1,%2,%3}, {%4,%5,%6,%7}, {%8,%9}, {%0,%1,%2,%3};"
        : "+f"(c[0]), "+f"(c[1]), "+f"(c[2]), "+f"(c[3])
        : "r"(a[0]), "r"(a[1]), "r"(a[2]), "r"(a[3]), "r"(b[0]), "r"(b[1]));
}

__device__ __forceinline__ void ldsm4(unsigned& r0, unsigned& r1, unsigned& r2, unsigned& r3,
                                      const void* p) {
    unsigned addr = (unsigned)__cvta_generic_to_shared(p);
    asm volatile("ldmatrix.sync.aligned.m8n8.x4.shared.b16 {%0,%1,%2,%3}, [%4];"
                 : "=r"(r0), "=r"(r1), "=r"(r2), "=r"(r3) : "r"(addr));
}

__device__ __forceinline__ void cpa16h(__half* dst, const __half* src, int bytes) {
    unsigned d = (unsigned)__cvta_generic_to_shared(dst);
    asm volatile("cp.async.cg.shared.global [%0], [%1], 16, %2;\n"
                 :: "r"(d), "l"(src), "r"(bytes));
}
__device__ __forceinline__ void cp_commit() { asm volatile("cp.async.commit_group;\n"); }
template<int N>
__device__ __forceinline__ void cp_wait() {
    asm volatile("cp.async.wait_group %0;\n" :: "n"(N));
}

// =================== fp16 tensor-core GEMM (BK=32, compile-time K) ==========
//   C[M,N] = act(A[M,KP] @ W[N,KP]^T + bias[N]*rowscale[M]), C stored __half.
//   ACT: 0=none, 1=leaky_relu(0.01), 2=elu.  KP: compile-time padded K.
// BM=BN=128, BK=32, 3 stages (48KB); 8 warps (2M x 4N), warp 64x32.
// Smem row = 32 halves (4 x 16B chunks); chunk c of row m at c ^ ((m>>1)&3).
// kt-loop fully unrolled (NK = 2/2/7): ptxas constant-folds all index math.
#define SBM 128
#define SBN 128
#define SBK 32
#define GSTG 3
#define EPS 136      // epilogue smem row stride in halves

template<int ACT, int KP>
__global__ void __launch_bounds__(256, 2)
gemm_h(const __half* __restrict__ A, const __half* __restrict__ W,
       const float* __restrict__ bias, const float* __restrict__ rowscale,
       __half* __restrict__ C, int M, int N)
{
    constexpr int NK = (KP + SBK - 1) / SBK;
    __shared__ __align__(16) __half smem_all[GSTG * (SBM + SBN) * SBK];
#define AS(S) ((__half(*)[SBK])(smem_all + (size_t)(S) * (SBM + SBN) * SBK))
#define BS(S) ((__half(*)[SBK])(smem_all + ((size_t)(S) * (SBM + SBN) + SBM) * SBK))

    const int tid   = threadIdx.x;
    const int lane  = tid & 31;
    const int warp  = tid >> 5;
    const int warpM = warp & 1;
    const int warpN = warp >> 1;
    const int mBase = blockIdx.y * SBM;
    const int nBase = blockIdx.x * SBN;
    const int r0 = lane >> 2;
    const int c0 = lane & 3;
    const int lrowA = ((lane >> 3) & 1) * 8 + (lane & 7);
    const int lchA  = lane >> 4;
    const int lrowB = (lane >> 4) * 8 + (lane & 7);
    const int lchB  = (lane >> 3) & 1;

    float acc[4][4][4];
    #pragma unroll
    for (int mt = 0; mt < 4; mt++)
        #pragma unroll
        for (int nt = 0; nt < 4; nt++)
            #pragma unroll
            for (int i = 0; i < 4; i++) acc[mt][nt][i] = 0.f;

#define LOAD(S, KT)                                                            \
    {                                                                          \
        const int kbase = (KT) * SBK;                                          \
        _Pragma("unroll")                                                      \
        for (int it = 0; it < 2; it++) {                                       \
            int e = tid + it * 256;                                            \
            int m = e >> 2, c = e & 3;                                         \
            int k0 = kbase + c * 8;                                            \
            int bytes = (k0 < KP) ? 16 : 0;                                    \
            const __half* src = A + (size_t)(mBase + m) * KP + (bytes ? k0 : 0);\
            cpa16h(&AS(S)[m][(c ^ ((m >> 1) & 3)) * 8], src, bytes);           \
        }                                                                      \
        _Pragma("unroll")                                                      \
        for (int it = 0; it < 2; it++) {                                       \
            int e = tid + it * 256;                                            \
            int n = e >> 2, c = e & 3;                                         \
            int gn = nBase + n, k0 = kbase + c * 8;                            \
            int bytes = (gn < N && k0 < KP) ? 16 : 0;                          \
            const __half* src = W + (size_t)(gn < N ? gn : 0) * KP             \
                                  + (bytes ? k0 : 0);                          \
            cpa16h(&BS(S)[n][(c ^ ((n >> 1) & 3)) * 8], src, bytes);           \
        }                                                                      \
        cp_commit();                                                           \
    }

    #pragma unroll
    for (int s = 0; s < GSTG - 1; s++) {
        if (s < NK) { LOAD(s, s); } else { cp_commit(); }
    }

    #pragma unroll
    for (int kt = 0; kt < NK; kt++) {
        const int st = kt % GSTG;
        cp_wait<GSTG - 2>();
        __syncthreads();

        if (kt + GSTG - 1 < NK) {
            LOAD((kt + GSTG - 1) % GSTG, kt + GSTG - 1);
        } else {
            cp_commit();
        }

        const __half (*as)[SBK] = AS(st);
        const __half (*bs)[SBK] = BS(st);

        #pragma unroll
        for (int hk = 0; hk < 2; hk++) {
            unsigned a[4][4];
            #pragma unroll
            for (int mt = 0; mt < 4; mt++) {
                int row = warpM * 64 + mt * 16 + lrowA;
                int ch = (hk * 2 + lchA) ^ ((row >> 1) & 3);
                ldsm4(a[mt][0], a[mt][1], a[mt][2], a[mt][3], &as[row][ch * 8]);
            }
            unsigned b[4][2];
            #pragma unroll
            for (int p = 0; p < 2; p++) {
                int row = warpN * 32 + p * 16 + lrowB;
                int ch = (hk * 2 + lchB) ^ ((row >> 1) & 3);
                unsigned t0, t1, t2, t3;
                ldsm4(t0, t1, t2, t3, &bs[row][ch * 8]);
                b[2 * p][0]     = t0; b[2 * p][1]     = t1;
                b[2 * p + 1][0] = t2; b[2 * p + 1][1] = t3;
            }
            #pragma unroll
            for (int mt = 0; mt < 4; mt++)
                #pragma unroll
                for (int nt = 0; nt < 4; nt++)
                    mma_f16(acc[mt][nt], a[mt], b[nt]);
        }
    }

    // -------- epilogue: bias+act -> padded smem -> coalesced STG.128 --------
    __syncthreads();
    __half* ep = smem_all;
    #pragma unroll
    for (int mt = 0; mt < 4; mt++) {
        int lr = warpM * 64 + mt * 16 + r0;
        int grow0 = mBase + lr;
        float s0 = rowscale ? rowscale[grow0]     : 1.f;
        float s1 = rowscale ? rowscale[grow0 + 8] : 1.f;
        #pragma unroll
        for (int nt = 0; nt < 4; nt++) {
            int lc  = warpN * 32 + nt * 8 + c0 * 2;
            int col = nBase + lc;
            float b0 = (col < N)     ? bias[col]     : 0.f;
            float b1 = (col + 1 < N) ? bias[col + 1] : 0.f;
            float v00 = acc[mt][nt][0] + b0 * s0;
            float v01 = acc[mt][nt][1] + b1 * s0;
            float v10 = acc[mt][nt][2] + b0 * s1;
            float v11 = acc[mt][nt][3] + b1 * s1;
            if (ACT == 1) {
                v00 = (v00 > 0.f) ? v00 : 0.01f * v00;
                v01 = (v01 > 0.f) ? v01 : 0.01f * v01;
                v10 = (v10 > 0.f) ? v10 : 0.01f * v10;
                v11 = (v11 > 0.f) ? v11 : 0.01f * v11;
            } else if (ACT == 2) {
                v00 = (v00 > 0.f) ? v00 : expm1f(v00);
                v01 = (v01 > 0.f) ? v01 : expm1f(v01);
                v10 = (v10 > 0.f) ? v10 : expm1f(v10);
                v11 = (v11 > 0.f) ? v11 : expm1f(v11);
            }
            *(half2*)&ep[(lr    ) * EPS + lc] = __floats2half2_rn(v00, v01);
            *(half2*)&ep[(lr + 8) * EPS + lc] = __floats2half2_rn(v10, v11);
        }
    }
    __syncthreads();
    for (int it = tid; it < SBM * 16; it += 256) {
        int r  = it >> 4, ck = it & 15;
        int gc = nBase + ck * 8;
        if (gc < N) {
            *(uint4*)&C[(size_t)(mBase + r) * N + gc] = *(const uint4*)&ep[r * EPS + ck * 8];
        }
    }
#undef LOAD
#undef AS
#undef BS
}

// =================== fused gi+gh GEMM + GRU epilogue (round-12 proven) ======
#define GBM 128
#define GNC 96
#define FSTG 4

__global__ void __launch_bounds__(256, 2)
gru_fused(const __half* __restrict__ ctx, const __half* __restrict__ cur,
          const __half* __restrict__ Wih, const __half* __restrict__ Whh,
          const float* __restrict__ bih, const float* __restrict__ bhh,
          __half* __restrict__ curout, float* __restrict__ outf, int finalr)
{
    __shared__ __align__(16) __half smraw[FSTG * (GBM + GBM + GNC) * 16];

    const int tid   = threadIdx.x;
    const int lane  = tid & 31;
    const int warp  = tid >> 5;
    const int warpM = warp & 3;
    const int warpN = warp >> 2;
    const int mBase = blockIdx.y * GBM;
    const int jBase = blockIdx.x * 16;
    const int nk    = (KPF + 15) / 16;  // 13
    const int r0 = lane >> 2;
    const int c0 = lane & 3;
    const int lrowA = ((lane >> 3) & 1) * 8 + (lane & 7);
    const int lchA  = lane >> 4;
    const int lrowB = (lane >> 4) * 8 + (lane & 7);
    const int lchB  = (lane >> 3) & 1;

    float acc[2][6][4];
    #pragma unroll
    for (int mt = 0; mt < 2; mt++)
        #pragma unroll
        for (int nt = 0; nt < 6; nt++)
            #pragma unroll
            for (int i = 0; i < 4; i++) acc[mt][nt][i] = 0.f;

#define SCTX(S) ((__half(*)[16])(smraw + (size_t)(S) * (GBM+GBM+GNC) * 16))
#define SCUR(S) ((__half(*)[16])(smraw + ((size_t)(S) * (GBM+GBM+GNC) + GBM) * 16))
#define SB(S)   ((__half(*)[16])(smraw + ((size_t)(S) * (GBM+GBM+GNC) + 2*GBM) * 16))

#define FLOAD(S, KT)                                                           \
    {                                                                          \
        int kbase = (KT) * 16;                                                 \
        {                                                                      \
            int m = tid >> 1, c = tid & 1;                                     \
            int k0 = kbase + c * 8;                                            \
            int bytes = (k0 < KPF) ? 16 : 0;                                   \
            size_t off = (size_t)(mBase + m) * KPF + (bytes ? k0 : 0);         \
            int sc = (c ^ ((m >> 2) & 1)) * 8;                                 \
            cpa16h(&SCTX(S)[m][sc], ctx + off, bytes);                         \
            cpa16h(&SCUR(S)[m][sc], cur + off, bytes);                         \
        }                                                                      \
        if (tid < 2 * GNC) {                                                   \
            int rn = tid >> 1, c = tid & 1;                                    \
            int gate = rn >> 4;                                                \
            int jj = jBase + (rn & 15);                                        \
            int k0 = kbase + c * 8;                                            \
            int bytes = (jj < FF && k0 < KPF) ? 16 : 0;                        \
            int jjc = (jj < FF) ? jj : 0;                                      \
            const __half* src = (gate < 3)                                     \
                ? Wih + ((size_t)gate * FF + jjc) * KPF                        \
                : Whh + ((size_t)(gate - 3) * FF + jjc) * KPF;                 \
            cpa16h(&SB(S)[rn][(c ^ ((rn >> 2) & 1)) * 8],                      \
                   src + (bytes ? k0 : 0), bytes);                             \
        }                                                                      \
        cp_commit();                                                           \
    }

    #pragma unroll
    for (int s = 0; s < FSTG - 1; s++) { FLOAD(s, s); }

    for (int kt = 0; kt < nk; kt++) {
        const int st = kt % FSTG;
        cp_wait<FSTG - 2>();
        __syncthreads();

        int ktn = kt + FSTG - 1;
        if (ktn < nk) { FLOAD(ktn % FSTG, ktn); } else { cp_commit(); }

        const __half (*amat)[16] = warpN ? SCUR(st) : SCTX(st);
        const __half (*bs)[16]   = SB(st);

        unsigned a[2][4];
        #pragma unroll
        for (int mt = 0; mt < 2; mt++) {
            int row = warpM * 32 + mt * 16 + lrowA;
            int swc = lchA ^ ((row >> 2) & 1);
            ldsm4(a[mt][0], a[mt][1], a[mt][2], a[mt][3], &amat[row][swc * 8]);
        }
        unsigned b[6][2];
        #pragma unroll
        for (int p = 0; p < 3; p++) {
            int row = warpN * 48 + p * 16 + lrowB;
            int swc = lchB ^ ((row >> 2) & 1);
            unsigned t0, t1, t2, t3;
            ldsm4(t0, t1, t2, t3, &bs[row][swc * 8]);
            b[2 * p][0]     = t0; b[2 * p][1]     = t1;
            b[2 * p + 1][0] = t2; b[2 * p + 1][1] = t3;
        }
        #pragma unroll
        for (int mt = 0; mt < 2; mt++)
            #pragma unroll
            for (int nt = 0; nt < 6; nt++)
                mma_f16(acc[mt][nt], a[mt], b[nt]);
    }

    // -------- exchange + GRU epilogue (paired half2/float2 stores) ----------
    __syncthreads();
    float* ex = (float*)smraw;
    if (warpN == 1) {
        int base = (warpM * 32 + lane) * 49;
        #pragma unroll
        for (int mt = 0; mt < 2; mt++)
            #pragma unroll
            for (int nt = 0; nt < 6; nt++)
                #pragma unroll
                for (int i = 0; i < 4; i++)
                    ex[base + mt * 24 + nt * 4 + i] = acc[mt][nt][i];
    }
    __syncthreads();
    if (warpN == 0) {
        int base = (warpM * 32 + lane) * 49;
        #pragma unroll
        for (int mt = 0; mt < 2; mt++) {
            #pragma unroll
            for (int jh = 0; jh < 2; jh++) {
                int j0 = jBase + jh * 8 + c0 * 2;
                if (j0 < FF) {
                    #pragma unroll
                    for (int hf = 0; hf < 2; hf++) {
                        int row = mBase + warpM * 32 + mt * 16 + r0 + hf * 8;
                        half2 cpair = *(const half2*)&cur[(size_t)row * FF + j0];
                        float hv[2];
                        #pragma unroll
                        for (int q = 0; q < 2; q++) {
                            int i = hf * 2 + q;
                            int j = j0 + q;
                            float ir  = acc[mt][0 + jh][i] + bih[j];
                            float iz  = acc[mt][2 + jh][i] + bih[FF + j];
                            float inn = acc[mt][4 + jh][i] + bih[2 * FF + j];
                            float hr  = ex[base + mt * 24 + (0 + jh) * 4 + i] + bhh[j];
                            float hz  = ex[base + mt * 24 + (2 + jh) * 4 + i] + bhh[FF + j];
                            float hn  = ex[base + mt * 24 + (4 + jh) * 4 + i] + bhh[2 * FF + j];
                            float r = 1.f / (1.f + expf(-(ir + hr)));
                            float z = 1.f / (1.f + expf(-(iz + hz)));
                            float n = tanhf(inn + r * hn);
                            float c = q ? __half2float(__high2half(cpair))
                                        : __half2float(__low2half(cpair));
                            float h = (1.f - z) * n + z * c;
                            hv[q] = (h > 0.f) ? h : 0.f;
                        }
                        if (finalr) {
                            float2 t; t.x = hv[0]; t.y = hv[1];
                            *(float2*)&outf[(size_t)row * FF + j0] = t;
                        } else {
                            *(half2*)&curout[(size_t)row * FF + j0] =
                                __floats2half2_rn(hv[0], hv[1]);
                        }
                    }
                }
            }
        }
    }
#undef FLOAD
#undef SCTX
#undef SCUR
#undef SB
}

// ---------------- single fused fp32->fp16 (padded) conversion ---------------
#define W2H_C0 (MROWS*KPA)
#define W2H_C1 (W2H_C0 + FF*KPA)
#define W2H_C2 (W2H_C1 + FF*KPC)
#define W2H_C3 (W2H_C2 + RR*FF*FF)
#define W2H_C4 (W2H_C3 + RR*3*FF*FF)
#define W2H_C5 (W2H_C4 + RR*3*FF*FF)

__global__ void w2h_all(const float* __restrict__ atom_list,
                        const float* __restrict__ atom_W,
                        const float* __restrict__ nbr_W,
                        const float* __restrict__ attend_W,
                        const float* __restrict__ gWih,
                        const float* __restrict__ gWhh,
                        __half* __restrict__ ha,  __half* __restrict__ haw,
                        __half* __restrict__ hnw, __half* __restrict__ hat,
                        __half* __restrict__ hwi, __half* __restrict__ hwh)
{
    int i = blockIdx.x * blockDim.x + threadIdx.x;
    if (i < W2H_C0) {
        int n = i / KPA, k = i - n * KPA;
        ha[i] = (k < FA_) ? __float2half_rn(atom_list[(size_t)n * FA_ + k]) : __half(0.f);
    } else if (i < W2H_C1) {
        int j = i - W2H_C0; int n = j / KPA, k = j - n * KPA;
        haw[j] = (k < FA_) ? __float2half_rn(atom_W[(size_t)n * FA_ + k]) : __half(0.f);
    } else if (i < W2H_C2) {
        int j = i - W2H_C1; int n = j / KPC, k = j - n * KPC;
        hnw[j] = (k < KC) ? __float2half_rn(nbr_W[(size_t)n * KC + k]) : __half(0.f);
    } else if (i < W2H_C3) {
        int j = i - W2H_C2; hat[j] = __float2half_rn(attend_W[j]);
    } else if (i < W2H_C4) {
        int j = i - W2H_C3; hwi[j] = __float2half_rn(gWih[j]);
    } else if (i < W2H_C5) {
        int j = i - W2H_C4; hwh[j] = __float2half_rn(gWhh[j]);
    }
}

// ---------------- gather concat(atom_nbr, bond_nbr) -> half [MSLOT, KPC] ----
__global__ void gather_acat_kernel(const float* __restrict__ atom_list,
                                   const float* __restrict__ bond_list,
                                   const int*   __restrict__ adeg,
                                   const int*   __restrict__ bdeg,
                                   __half* __restrict__ acat)
{
    int e = blockIdx.x * blockDim.x + threadIdx.x;
    if (e >= MSLOT * KPC) return;
    int slot = e / KPC;
    int k    = e - slot * KPC;
    int b    = slot / (LSEQ * DD);
    float v = 0.f;
    if (k < FA_) {
        int a = adeg[slot];
        v = atom_list[((size_t)b * LSEQ + a) * FA_ + k];
    } else if (k < KC) {
        int bb = bdeg[slot];
        v = bond_list[((size_t)b * LSEQ + bb) * FB_ + (k - FA_)];
    }
    acat[e] = __float2half_rn(v);
}

// ---------------- attention: warp per row ------------------------------------
__global__ void __launch_bounds__(256)
attention_kernel(const __half* __restrict__ cur,
                 const __half* __restrict__ nbrfeat,
                 const int*    __restrict__ adeg,
                 const float*  __restrict__ alignW,
                 const float*  __restrict__ alignB,
                 __half* __restrict__ ctxpre,
                 float*  __restrict__ srow,
                 int first)
{
    int gw   = (blockIdx.x * blockDim.x + threadIdx.x) >> 5;
    int lane = threadIdx.x & 31;
    if (gw >= MROWS) return;
    const int r = gw;
    const int b = r >> 7;
    const float ab = alignB[0];

    float cv[7], a0[7], a1[7];
    #pragma unroll
    for (int i = 0; i < 7; i++) {
        int idx = lane + 32 * i;
        bool ok = idx < FF;
        cv[i] = ok ? __half2float(cur[(size_t)r * FF + idx]) : 0.f;
        a0[i] = ok ? alignW[idx]      : 0.f;
        a1[i] = ok ? alignW[FF + idx] : 0.f;
    }
    float qd = 0.f;
    #pragma unroll
    for (int i = 0; i < 7; i++) qd += cv[i] * a0[i];
    #pragma unroll
    for (int o = 16; o > 0; o >>= 1) qd += __shfl_xor_sync(0xffffffffu, qd, o);

    float nv[DD][7];
    float score[DD];
    int   nai[DD];

    #pragma unroll
    for (int d = 0; d < DD; d++) {
        int na = adeg[r * DD + d];
        nai[d] = na;
        const __half* np = first ? (nbrfeat + ((size_t)r * DD + d) * FF)
                                 : (cur + ((size_t)(b * LSEQ + na)) * FF);
        float nd = 0.f;
        #pragma unroll
        for (int i = 0; i < 7; i++) {
            int idx = lane + 32 * i;
            float v = (idx < FF) ? __half2float(np[idx]) : 0.f;
            nv[d][i] = v;
            nd += v * a1[i];
        }
        #pragma unroll
        for (int o = 16; o > 0; o >>= 1) nd += __shfl_xor_sync(0xffffffffu, nd, o);
        float sc = qd + nd + ab;
        sc = (sc > 0.f) ? sc : 0.01f * sc;
        if (na == LSEQ - 1) sc = sc - 9e8f;
        score[d] = sc;
    }

    float mx = score[0];
    #pragma unroll
    for (int d = 1; d < DD; d++) mx = fmaxf(mx, score[d]);
    float e[DD], den = 0.f;
    #pragma unroll
    for (int d = 0; d < DD; d++) { e[d] = expf(score[d] - mx); den += e[d]; }
    float inv = 1.f / den;
    float s = 0.f;
    #pragma unroll
    for (int d = 0; d < DD; d++) {
        float a = e[d] * inv;
        if (nai[d] == LSEQ - 1) a = 0.f;
        e[d] = a;
        s += a;
    }

    #pragma unroll
    for (int i = 0; i < 7; i++) {
        int idx = lane + 32 * i;
        if (idx < FF) {
            float v = 0.f;
            #pragma unroll
            for (int d = 0; d < DD; d++) v += e[d] * nv[d][i];
            ctxpre[(size_t)r * FF + idx] = __float2half_rn(v);
        }
    }
    if (lane == 0) srow[r] = s;
}

// ---------------- launch ------------------------------------------------------
static inline int ceil_div(int a, int b) { return (a + b - 1) / b; }

extern "C" void kernel_launch(void* const* d_in, const int* in_sizes, int n_in,
                              void* d_out, int out_size)
{
    const float* atom_list = (const float*)d_in[0];
    const float* bond_list = (const float*)d_in[1];
    const int*   adeg      = (const int*)  d_in[2];
    const int*   bdeg      = (const int*)  d_in[3];
    const float* atom_W    = (const float*)d_in[4];
    const float* atom_b    = (const float*)d_in[5];
    const float* nbr_W     = (const float*)d_in[6];
    const float* nbr_b     = (const float*)d_in[7];
    const float* align_W   = (const float*)d_in[8];
    const float* align_b   = (const float*)d_in[9];
    const float* attend_W  = (const float*)d_in[10];
    const float* attend_b  = (const float*)d_in[11];
    const float* gWih      = (const float*)d_in[12];
    const float* gWhh      = (const float*)d_in[13];
    const float* gbih      = (const float*)d_in[14];
    const float* gbhh      = (const float*)d_in[15];
    float* out = (float*)d_out;

    __half *cur, *cur2, *ctxpre, *ctx, *nbr, *acat, *atomh;
    __half *atomWh, *nbrWh, *attWh, *Wihh, *Whhh;
    float *s;
    cudaGetSymbolAddress((void**)&cur,    h_cur);
    cudaGetSymbolAddress((void**)&cur2,   h_cur2);
    cudaGetSymbolAddress((void**)&ctxpre, h_ctxpre);
    cudaGetSymbolAddress((void**)&ctx,    h_ctx);
    cudaGetSymbolAddress((void**)&s,      g_s);
    cudaGetSymbolAddress((void**)&nbr,    h_nbr);
    cudaGetSymbolAddress((void**)&acat,   h_acat);
    cudaGetSymbolAddress((void**)&atomh,  h_atom);
    cudaGetSymbolAddress((void**)&atomWh, h_atomW);
    cudaGetSymbolAddress((void**)&nbrWh,  h_nbrW);
    cudaGetSymbolAddress((void**)&attWh,  h_attW);
    cudaGetSymbolAddress((void**)&Wihh,   h_Wih);
    cudaGetSymbolAddress((void**)&Whhh,   h_Whh);

    // 1. fused fp16 conversion of all GEMM operands
    w2h_all<<<ceil_div(W2H_C5, 256), 256>>>(
        atom_list, atom_W, nbr_W, attend_W, gWih, gWhh,
        atomh, atomWh, nbrWh, attWh, Wihh, Whhh);

    // 2. cur = leaky(atom_list @ atom_W^T + atom_b)
    gemm_h<1, KPA><<<dim3(ceil_div(FF, SBN), MROWS / SBM), 256>>>(
        atomh, atomWh, atom_b, nullptr, cur, MROWS, FF);

    // 3. gather concat inputs
    gather_acat_kernel<<<ceil_div(MSLOT * KPC, 256), 256>>>(
        atom_list, bond_list, adeg, bdeg, acat);

    // 4. nbrfeat = leaky(acat @ nbr_W^T + nbr_b)
    gemm_h<1, KPC><<<dim3(ceil_div(FF, SBN), MSLOT / SBM), 256>>>(
        acat, nbrWh, nbr_b, nullptr, nbr, MSLOT, FF);

    __half* curbuf[2] = { cur, cur2 };
    for (int d = 0; d < RR; d++) {
        __half* curin   = curbuf[d & 1];
        __half* curoutp = curbuf[(d + 1) & 1];

        attention_kernel<<<MROWS / 8, 256>>>(
            curin, nbr, adeg,
            align_W + (size_t)d * 2 * FF, align_b + d,
            ctxpre, s, (d == 0) ? 1 : 0);

        // launch #6 (round 0) -> captured by ncu (-s 5 -c 1)
        gemm_h<2, KPF><<<dim3(ceil_div(FF, SBN), MROWS / SBM), 256>>>(
            ctxpre, attWh + (size_t)d * FF * FF, attend_b + (size_t)d * FF, s,
            ctx, MROWS, FF);

        gru_fused<<<dim3(13, MROWS / GBM), 256>>>(
            ctx, curin,
            Wihh + (size_t)d * 3 * FF * FF, Whhh + (size_t)d * 3 * FF * FF,
            gbih + (size_t)d * 3 * FF, gbhh + (size_t)d * 3 * FF,
            curoutp, out, (d == RR - 1) ? 1 : 0);
    }
}

// round 16
// speedup vs baseline: 1.2191x; 1.1638x over previous
#include <cuda_runtime.h>
#include <cuda_fp16.h>
#include <cstddef>

// Problem constants
#define BATCH 256
#define LSEQ  128
#define DD    6
#define FF    200
#define FA_   39
#define FB_   10
#define RR    2
#define MROWS (BATCH*LSEQ)          // 32768
#define KC    (FA_+FB_)             // 49
#define KPA   40                    // padded K for atom-side GEMMs
#define KPB   16                    // padded K for bond-side GEMM
#define KPF   200                   // F

// ---------------- scratch (device globals; no allocations allowed) ----------
__device__ __half h_cur   [(size_t)MROWS*FF];
__device__ __half h_cur2  [(size_t)MROWS*FF];
__device__ __half h_ctxpre[(size_t)MROWS*FF];
__device__ __half h_ctx   [(size_t)MROWS*FF];   // also bpart before round 0
__device__ __half h_apart [(size_t)MROWS*FF];
__device__ float  g_s     [MROWS];
__device__ __half h_atom  [(size_t)MROWS*KPA];
__device__ __half h_bondl [(size_t)MROWS*KPB];
__device__ __half h_atomW [FF*KPA];
__device__ __half h_nbrWa [FF*KPA];
__device__ __half h_nbrWb [FF*KPB];
__device__ __half h_attW  [RR*FF*FF];
__device__ __half h_Wih   [(size_t)RR*3*FF*FF];
__device__ __half h_Whh   [(size_t)RR*3*FF*FF];

// ---------------- PTX helpers ------------------------------------------------
__device__ __forceinline__ void mma_f16(float* c, const unsigned* a, const unsigned* b) {
    asm volatile(
        "mma.sync.aligned.m16n8k16.row.col.f32.f16.f16.f32 "
        "{%0,%1,%2,%3}, {%4,%5,%6,%7}, {%8,%9}, {%0,%1,%2,%3};"
        : "+f"(c[0]), "+f"(c[1]), "+f"(c[2]), "+f"(c[3])
        : "r"(a[0]), "r"(a[1]), "r"(a[2]), "r"(a[3]), "r"(b[0]), "r"(b[1]));
}

__device__ __forceinline__ void ldsm4(unsigned& r0, unsigned& r1, unsigned& r2, unsigned& r3,
                                      const void* p) {
    unsigned addr = (unsigned)__cvta_generic_to_shared(p);
    asm volatile("ldmatrix.sync.aligned.m8n8.x4.shared.b16 {%0,%1,%2,%3}, [%4];"
                 : "=r"(r0), "=r"(r1), "=r"(r2), "=r"(r3) : "r"(addr));
}

__device__ __forceinline__ void cpa16h(__half* dst, const __half* src, int bytes) {
    unsigned d = (unsigned)__cvta_generic_to_shared(dst);
    asm volatile("cp.async.cg.shared.global [%0], [%1], 16, %2;\n"
                 :: "r"(d), "l"(src), "r"(bytes));
}
__device__ __forceinline__ void cp_commit() { asm volatile("cp.async.commit_group;\n"); }
template<int N>
__device__ __forceinline__ void cp_wait() {
    asm volatile("cp.async.wait_group %0;\n" :: "n"(N));
}

// =================== fp16 tensor-core GEMM (BK=32, compile-time K) ==========
//   C[M,N] = act(A[M,KP] @ W[N,KP]^T + bias[N]*rowscale[M]), C stored __half.
//   ACT: 0=none, 1=leaky_relu(0.01), 2=elu.  bias may be null.
#define SBM 128
#define SBN 128
#define SBK 32
#define GSTG 3
#define EPS 136

template<int ACT, int KP>
__global__ void __launch_bounds__(256, 2)
gemm_h(const __half* __restrict__ A, const __half* __restrict__ W,
       const float* __restrict__ bias, const float* __restrict__ rowscale,
       __half* __restrict__ C, int M, int N)
{
    constexpr int NK = (KP + SBK - 1) / SBK;
    __shared__ __align__(16) __half smem_all[GSTG * (SBM + SBN) * SBK];
#define AS(S) ((__half(*)[SBK])(smem_all + (size_t)(S) * (SBM + SBN) * SBK))
#define BS(S) ((__half(*)[SBK])(smem_all + ((size_t)(S) * (SBM + SBN) + SBM) * SBK))

    const int tid   = threadIdx.x;
    const int lane  = tid & 31;
    const int warp  = tid >> 5;
    const int warpM = warp & 1;
    const int warpN = warp >> 1;
    const int mBase = blockIdx.y * SBM;
    const int nBase = blockIdx.x * SBN;
    const int r0 = lane >> 2;
    const int c0 = lane & 3;
    const int lrowA = ((lane >> 3) & 1) * 8 + (lane & 7);
    const int lchA  = lane >> 4;
    const int lrowB = (lane >> 4) * 8 + (lane & 7);
    const int lchB  = (lane >> 3) & 1;

    float acc[4][4][4];
    #pragma unroll
    for (int mt = 0; mt < 4; mt++)
        #pragma unroll
        for (int nt = 0; nt < 4; nt++)
            #pragma unroll
            for (int i = 0; i < 4; i++) acc[mt][nt][i] = 0.f;

#define LOAD(S, KT)                                                            \
    {                                                                          \
        const int kbase = (KT) * SBK;                                          \
        _Pragma("unroll")                                                      \
        for (int it = 0; it < 2; it++) {                                       \
            int e = tid + it * 256;                                            \
            int m = e >> 2, c = e & 3;                                         \
            int k0 = kbase + c * 8;                                            \
            int bytes = (k0 < KP) ? 16 : 0;                                    \
            const __half* src = A + (size_t)(mBase + m) * KP + (bytes ? k0 : 0);\
            cpa16h(&AS(S)[m][(c ^ ((m >> 1) & 3)) * 8], src, bytes);           \
        }                                                                      \
        _Pragma("unroll")                                                      \
        for (int it = 0; it < 2; it++) {                                       \
            int e = tid + it * 256;                                            \
            int n = e >> 2, c = e & 3;                                         \
            int gn = nBase + n, k0 = kbase + c * 8;                            \
            int bytes = (gn < N && k0 < KP) ? 16 : 0;                          \
            const __half* src = W + (size_t)(gn < N ? gn : 0) * KP             \
                                  + (bytes ? k0 : 0);                          \
            cpa16h(&BS(S)[n][(c ^ ((n >> 1) & 3)) * 8], src, bytes);           \
        }                                                                      \
        cp_commit();                                                           \
    }

    #pragma unroll
    for (int s = 0; s < GSTG - 1; s++) {
        if (s < NK) { LOAD(s, s); } else { cp_commit(); }
    }

    #pragma unroll
    for (int kt = 0; kt < NK; kt++) {
        const int st = kt % GSTG;
        cp_wait<GSTG - 2>();
        __syncthreads();

        if (kt + GSTG - 1 < NK) {
            LOAD((kt + GSTG - 1) % GSTG, kt + GSTG - 1);
        } else {
            cp_commit();
        }

        const __half (*as)[SBK] = AS(st);
        const __half (*bs)[SBK] = BS(st);

        #pragma unroll
        for (int hk = 0; hk < 2; hk++) {
            unsigned a[4][4];
            #pragma unroll
            for (int mt = 0; mt < 4; mt++) {
                int row = warpM * 64 + mt * 16 + lrowA;
                int ch = (hk * 2 + lchA) ^ ((row >> 1) & 3);
                ldsm4(a[mt][0], a[mt][1], a[mt][2], a[mt][3], &as[row][ch * 8]);
            }
            unsigned b[4][2];
            #pragma unroll
            for (int p = 0; p < 2; p++) {
                int row = warpN * 32 + p * 16 + lrowB;
                int ch = (hk * 2 + lchB) ^ ((row >> 1) & 3);
                unsigned t0, t1, t2, t3;
                ldsm4(t0, t1, t2, t3, &bs[row][ch * 8]);
                b[2 * p][0]     = t0; b[2 * p][1]     = t1;
                b[2 * p + 1][0] = t2; b[2 * p + 1][1] = t3;
            }
            #pragma unroll
            for (int mt = 0; mt < 4; mt++)
                #pragma unroll
                for (int nt = 0; nt < 4; nt++)
                    mma_f16(acc[mt][nt], a[mt], b[nt]);
        }
    }

    // -------- epilogue: bias+act -> padded smem -> coalesced STG.128 --------
    __syncthreads();
    __half* ep = smem_all;
    #pragma unroll
    for (int mt = 0; mt < 4; mt++) {
        int lr = warpM * 64 + mt * 16 + r0;
        int grow0 = mBase + lr;
        float s0 = rowscale ? rowscale[grow0]     : 1.f;
        float s1 = rowscale ? rowscale[grow0 + 8] : 1.f;
        #pragma unroll
        for (int nt = 0; nt < 4; nt++) {
            int lc  = warpN * 32 + nt * 8 + c0 * 2;
            int col = nBase + lc;
            float b0 = (bias && col < N)     ? bias[col]     : 0.f;
            float b1 = (bias && col + 1 < N) ? bias[col + 1] : 0.f;
            float v00 = acc[mt][nt][0] + b0 * s0;
            float v01 = acc[mt][nt][1] + b1 * s0;
            float v10 = acc[mt][nt][2] + b0 * s1;
            float v11 = acc[mt][nt][3] + b1 * s1;
            if (ACT == 1) {
                v00 = (v00 > 0.f) ? v00 : 0.01f * v00;
                v01 = (v01 > 0.f) ? v01 : 0.01f * v01;
                v10 = (v10 > 0.f) ? v10 : 0.01f * v10;
                v11 = (v11 > 0.f) ? v11 : 0.01f * v11;
            } else if (ACT == 2) {
                v00 = (v00 > 0.f) ? v00 : expm1f(v00);
                v01 = (v01 > 0.f) ? v01 : expm1f(v01);
                v10 = (v10 > 0.f) ? v10 : expm1f(v10);
                v11 = (v11 > 0.f) ? v11 : expm1f(v11);
            }
            *(half2*)&ep[(lr    ) * EPS + lc] = __floats2half2_rn(v00, v01);
            *(half2*)&ep[(lr + 8) * EPS + lc] = __floats2half2_rn(v10, v11);
        }
    }
    __syncthreads();
    for (int it = tid; it < SBM * 16; it += 256) {
        int r  = it >> 4, ck = it & 15;
        int gc = nBase + ck * 8;
        if (gc < N) {
            *(uint4*)&C[(size_t)(mBase + r) * N + gc] = *(const uint4*)&ep[r * EPS + ck * 8];
        }
    }
#undef LOAD
#undef AS
#undef BS
}

// =================== fused gi+gh GEMM + GRU epilogue =========================
#define GBM 128
#define GNC 96
#define FSTG 4

__global__ void __launch_bounds__(256, 2)
gru_fused(const __half* __restrict__ ctx, const __half* __restrict__ cur,
          const __half* __restrict__ Wih, const __half* __restrict__ Whh,
          const float* __restrict__ bih, const float* __restrict__ bhh,
          __half* __restrict__ curout, float* __restrict__ outf, int finalr)
{
    __shared__ __align__(16) __half smraw[FSTG * (GBM + GBM + GNC) * 16];

    const int tid   = threadIdx.x;
    const int lane  = tid & 31;
    const int warp  = tid >> 5;
    const int warpM = warp & 3;
    const int warpN = warp >> 2;
    const int mBase = blockIdx.y * GBM;
    const int jBase = blockIdx.x * 16;
    const int nk    = (KPF + 15) / 16;  // 13
    const int r0 = lane >> 2;
    const int c0 = lane & 3;
    const int lrowA = ((lane >> 3) & 1) * 8 + (lane & 7);
    const int lchA  = lane >> 4;
    const int lrowB = (lane >> 4) * 8 + (lane & 7);
    const int lchB  = (lane >> 3) & 1;

    float acc[2][6][4];
    #pragma unroll
    for (int mt = 0; mt < 2; mt++)
        #pragma unroll
        for (int nt = 0; nt < 6; nt++)
            #pragma unroll
            for (int i = 0; i < 4; i++) acc[mt][nt][i] = 0.f;

#define SCTX(S) ((__half(*)[16])(smraw + (size_t)(S) * (GBM+GBM+GNC) * 16))
#define SCUR(S) ((__half(*)[16])(smraw + ((size_t)(S) * (GBM+GBM+GNC) + GBM) * 16))
#define SB(S)   ((__half(*)[16])(smraw + ((size_t)(S) * (GBM+GBM+GNC) + 2*GBM) * 16))

#define FLOAD(S, KT)                                                           \
    {                                                                          \
        int kbase = (KT) * 16;                                                 \
        {                                                                      \
            int m = tid >> 1, c = tid & 1;                                     \
            int k0 = kbase + c * 8;                                            \
            int bytes = (k0 < KPF) ? 16 : 0;                                   \
            size_t off = (size_t)(mBase + m) * KPF + (bytes ? k0 : 0);         \
            int sc = (c ^ ((m >> 2) & 1)) * 8;                                 \
            cpa16h(&SCTX(S)[m][sc], ctx + off, bytes);                         \
            cpa16h(&SCUR(S)[m][sc], cur + off, bytes);                         \
        }                                                                      \
        if (tid < 2 * GNC) {                                                   \
            int rn = tid >> 1, c = tid & 1;                                    \
            int gate = rn >> 4;                                                \
            int jj = jBase + (rn & 15);                                        \
            int k0 = kbase + c * 8;                                            \
            int bytes = (jj < FF && k0 < KPF) ? 16 : 0;                        \
            int jjc = (jj < FF) ? jj : 0;                                      \
            const __half* src = (gate < 3)                                     \
                ? Wih + ((size_t)gate * FF + jjc) * KPF                        \
                : Whh + ((size_t)(gate - 3) * FF + jjc) * KPF;                 \
            cpa16h(&SB(S)[rn][(c ^ ((rn >> 2) & 1)) * 8],                      \
                   src + (bytes ? k0 : 0), bytes);                             \
        }                                                                      \
        cp_commit();                                                           \
    }

    #pragma unroll
    for (int s = 0; s < FSTG - 1; s++) { FLOAD(s, s); }

    for (int kt = 0; kt < nk; kt++) {
        const int st = kt % FSTG;
        cp_wait<FSTG - 2>();
        __syncthreads();

        int ktn = kt + FSTG - 1;
        if (ktn < nk) { FLOAD(ktn % FSTG, ktn); } else { cp_commit(); }

        const __half (*amat)[16] = warpN ? SCUR(st) : SCTX(st);
        const __half (*bs)[16]   = SB(st);

        unsigned a[2][4];
        #pragma unroll
        for (int mt = 0; mt < 2; mt++) {
            int row = warpM * 32 + mt * 16 + lrowA;
            int swc = lchA ^ ((row >> 2) & 1);
            ldsm4(a[mt][0], a[mt][1], a[mt][2], a[mt][3], &amat[row][swc * 8]);
        }
        unsigned b[6][2];
        #pragma unroll
        for (int p = 0; p < 3; p++) {
            int row = warpN * 48 + p * 16 + lrowB;
            int swc = lchB ^ ((row >> 2) & 1);
            unsigned t0, t1, t2, t3;
            ldsm4(t0, t1, t2, t3, &bs[row][swc * 8]);
            b[2 * p][0]     = t0; b[2 * p][1]     = t1;
            b[2 * p + 1][0] = t2; b[2 * p + 1][1] = t3;
        }
        #pragma unroll
        for (int mt = 0; mt < 2; mt++)
            #pragma unroll
            for (int nt = 0; nt < 6; nt++)
                mma_f16(acc[mt][nt], a[mt], b[nt]);
    }

    // -------- exchange + GRU epilogue (paired half2/float2 stores) ----------
    __syncthreads();
    float* ex = (float*)smraw;
    if (warpN == 1) {
        int base = (warpM * 32 + lane) * 49;
        #pragma unroll
        for (int mt = 0; mt < 2; mt++)
            #pragma unroll
            for (int nt = 0; nt < 6; nt++)
                #pragma unroll
                for (int i = 0; i < 4; i++)
                    ex[base + mt * 24 + nt * 4 + i] = acc[mt][nt][i];
    }
    __syncthreads();
    if (warpN == 0) {
        int base = (warpM * 32 + lane) * 49;
        #pragma unroll
        for (int mt = 0; mt < 2; mt++) {
            #pragma unroll
            for (int jh = 0; jh < 2; jh++) {
                int j0 = jBase + jh * 8 + c0 * 2;
                if (j0 < FF) {
                    #pragma unroll
                    for (int hf = 0; hf < 2; hf++) {
                        int row = mBase + warpM * 32 + mt * 16 + r0 + hf * 8;
                        half2 cpair = *(const half2*)&cur[(size_t)row * FF + j0];
                        float hv[2];
                        #pragma unroll
                        for (int q = 0; q < 2; q++) {
                            int i = hf * 2 + q;
                            int j = j0 + q;
                            float ir  = acc[mt][0 + jh][i] + bih[j];
                            float iz  = acc[mt][2 + jh][i] + bih[FF + j];
                            float inn = acc[mt][4 + jh][i] + bih[2 * FF + j];
                            float hr  = ex[base + mt * 24 + (0 + jh) * 4 + i] + bhh[j];
                            float hz  = ex[base + mt * 24 + (2 + jh) * 4 + i] + bhh[FF + j];
                            float hn  = ex[base + mt * 24 + (4 + jh) * 4 + i] + bhh[2 * FF + j];
                            float r = 1.f / (1.f + expf(-(ir + hr)));
                            float z = 1.f / (1.f + expf(-(iz + hz)));
                            float n = tanhf(inn + r * hn);
                            float c = q ? __half2float(__high2half(cpair))
                                        : __half2float(__low2half(cpair));
                            float h = (1.f - z) * n + z * c;
                            hv[q] = (h > 0.f) ? h : 0.f;
                        }
                        if (finalr) {
                            float2 t; t.x = hv[0]; t.y = hv[1];
                            *(float2*)&outf[(size_t)row * FF + j0] = t;
                        } else {
                            *(half2*)&curout[(size_t)row * FF + j0] =
                                __floats2half2_rn(hv[0], hv[1]);
                        }
                    }
                }
            }
        }
    }
#undef FLOAD
#undef SCTX
#undef SCUR
#undef SB
}

// ---------------- single fused fp32->fp16 (padded) conversion ---------------
#define W2H_C0 (MROWS*KPA)                 // atom_list
#define W2H_C1 (W2H_C0 + MROWS*KPB)        // bond_list
#define W2H_C2 (W2H_C1 + FF*KPA)           // atom_W
#define W2H_C3 (W2H_C2 + FF*KPA)           // nbr_W atom half
#define W2H_C4 (W2H_C3 + FF*KPB)           // nbr_W bond half
#define W2H_C5 (W2H_C4 + RR*FF*FF)         // attend_W
#define W2H_C6 (W2H_C5 + RR*3*FF*FF)       // gWih
#define W2H_C7 (W2H_C6 + RR*3*FF*FF)       // gWhh

__global__ void w2h_all(const float* __restrict__ atom_list,
                        const float* __restrict__ bond_list,
                        const float* __restrict__ atom_W,
                        const float* __restrict__ nbr_W,
                        const float* __restrict__ attend_W,
                        const float* __restrict__ gWih,
                        const float* __restrict__ gWhh,
                        __half* __restrict__ ha,   __half* __restrict__ hb,
                        __half* __restrict__ haw,
                        __half* __restrict__ hwa,  __half* __restrict__ hwb,
                        __half* __restrict__ hat,
                        __half* __restrict__ hwi,  __half* __restrict__ hwh)
{
    int i = blockIdx.x * blockDim.x + threadIdx.x;
    if (i < W2H_C0) {
        int n = i / KPA, k = i - n * KPA;
        ha[i] = (k < FA_) ? __float2half_rn(atom_list[(size_t)n * FA_ + k]) : __half(0.f);
    } else if (i < W2H_C1) {
        int j = i - W2H_C0; int n = j / KPB, k = j - n * KPB;
        hb[j] = (k < FB_) ? __float2half_rn(bond_list[(size_t)n * FB_ + k]) : __half(0.f);
    } else if (i < W2H_C2) {
        int j = i - W2H_C1; int n = j / KPA, k = j - n * KPA;
        haw[j] = (k < FA_) ? __float2half_rn(atom_W[(size_t)n * FA_ + k]) : __half(0.f);
    } else if (i < W2H_C3) {
        int j = i - W2H_C2; int n = j / KPA, k = j - n * KPA;
        hwa[j] = (k < FA_) ? __float2half_rn(nbr_W[(size_t)n * KC + k]) : __half(0.f);
    } else if (i < W2H_C4) {
        int j = i - W2H_C3; int n = j / KPB, k = j - n * KPB;
        hwb[j] = (k < FB_) ? __float2half_rn(nbr_W[(size_t)n * KC + FA_ + k]) : __half(0.f);
    } else if (i < W2H_C5) {
        int j = i - W2H_C4; hat[j] = __float2half_rn(attend_W[j]);
    } else if (i < W2H_C6) {
        int j = i - W2H_C5; hwi[j] = __float2half_rn(gWih[j]);
    } else if (i < W2H_C7) {
        int j = i - W2H_C6; hwh[j] = __float2half_rn(gWhh[j]);
    }
}

// ---------------- attention: warp per row ------------------------------------
// Round 0: nbr_feat[d] = leaky(apart[adeg] + bpart[bdeg])  (bias in apart)
// Round>0: nbr_feat[d] = cur[adeg]
__global__ void __launch_bounds__(256)
attention_kernel(const __half* __restrict__ cur,
                 const __half* __restrict__ apart,
                 const __half* __restrict__ bpart,
                 const int*    __restrict__ adeg,
                 const int*    __restrict__ bdeg,
                 const float*  __restrict__ alignW,
                 const float*  __restrict__ alignB,
                 __half* __restrict__ ctxpre,
                 float*  __restrict__ srow,
                 int first)
{
    int gw   = (blockIdx.x * blockDim.x + threadIdx.x) >> 5;
    int lane = threadIdx.x & 31;
    if (gw >= MROWS) return;
    const int r = gw;
    const int b = r >> 7;
    const float ab = alignB[0];

    float cv[7], a0[7], a1[7];
    #pragma unroll
    for (int i = 0; i < 7; i++) {
        int idx = lane + 32 * i;
        bool ok = idx < FF;
        cv[i] = ok ? __half2float(cur[(size_t)r * FF + idx]) : 0.f;
        a0[i] = ok ? alignW[idx]      : 0.f;
        a1[i] = ok ? alignW[FF + idx] : 0.f;
    }
    float qd = 0.f;
    #pragma unroll
    for (int i = 0; i < 7; i++) qd += cv[i] * a0[i];
    #pragma unroll
    for (int o = 16; o > 0; o >>= 1) qd += __shfl_xor_sync(0xffffffffu, qd, o);

    float nv[DD][7];
    float score[DD];
    int   nai[DD];

    #pragma unroll
    for (int d = 0; d < DD; d++) {
        int na = adeg[r * DD + d];
        nai[d] = na;
        float nd = 0.f;
        if (first) {
            int nb = bdeg[r * DD + d];
            const __half* ap = apart + (size_t)(b * LSEQ + na) * FF;
            const __half* bp = bpart + (size_t)(b * LSEQ + nb) * FF;
            #pragma unroll
            for (int i = 0; i < 7; i++) {
                int idx = lane + 32 * i;
                float v = 0.f;
                if (idx < FF) {
                    v = __half2float(ap[idx]) + __half2float(bp[idx]);
                    v = (v > 0.f) ? v : 0.01f * v;   // leaky_relu of nbr_feat
                }
                nv[d][i] = v;
                nd += v * a1[i];
            }
        } else {
            const __half* np = cur + (size_t)(b * LSEQ + na) * FF;
            #pragma unroll
            for (int i = 0; i < 7; i++) {
                int idx = lane + 32 * i;
                float v = (idx < FF) ? __half2float(np[idx]) : 0.f;
                nv[d][i] = v;
                nd += v * a1[i];
            }
        }
        #pragma unroll
        for (int o = 16; o > 0; o >>= 1) nd += __shfl_xor_sync(0xffffffffu, nd, o);
        float sc = qd + nd + ab;
        sc = (sc > 0.f) ? sc : 0.01f * sc;   // leaky_relu of align score
        if (na == LSEQ - 1) sc = sc - 9e8f;  // softmax mask (pad)
        score[d] = sc;
    }

    float mx = score[0];
    #pragma unroll
    for (int d = 1; d < DD; d++) mx = fmaxf(mx, score[d]);
    float e[DD], den = 0.f;
    #pragma unroll
    for (int d = 0; d < DD; d++) { e[d] = expf(score[d] - mx); den += e[d]; }
    float inv = 1.f / den;
    float s = 0.f;
    #pragma unroll
    for (int d = 0; d < DD; d++) {
        float a = e[d] * inv;
        if (nai[d] == LSEQ - 1) a = 0.f;     // attend mask
        e[d] = a;
        s += a;
    }

    #pragma unroll
    for (int i = 0; i < 7; i++) {
        int idx = lane + 32 * i;
        if (idx < FF) {
            float v = 0.f;
            #pragma unroll
            for (int d = 0; d < DD; d++) v += e[d] * nv[d][i];
            ctxpre[(size_t)r * FF + idx] = __float2half_rn(v);
        }
    }
    if (lane == 0) srow[r] = s;
}

// ---------------- launch ------------------------------------------------------
static inline int ceil_div(int a, int b) { return (a + b - 1) / b; }

extern "C" void kernel_launch(void* const* d_in, const int* in_sizes, int n_in,
                              void* d_out, int out_size)
{
    const float* atom_list = (const float*)d_in[0];
    const float* bond_list = (const float*)d_in[1];
    const int*   adeg      = (const int*)  d_in[2];
    const int*   bdeg      = (const int*)  d_in[3];
    const float* atom_W    = (const float*)d_in[4];
    const float* atom_b    = (const float*)d_in[5];
    const float* nbr_W     = (const float*)d_in[6];
    const float* nbr_b     = (const float*)d_in[7];
    const float* align_W   = (const float*)d_in[8];
    const float* align_b   = (const float*)d_in[9];
    const float* attend_W  = (const float*)d_in[10];
    const float* attend_b  = (const float*)d_in[11];
    const float* gWih      = (const float*)d_in[12];
    const float* gWhh      = (const float*)d_in[13];
    const float* gbih      = (const float*)d_in[14];
    const float* gbhh      = (const float*)d_in[15];
    float* out = (float*)d_out;

    __half *cur, *cur2, *ctxpre, *ctx, *apart, *atomh, *bondh;
    __half *atomWh, *nbrWa, *nbrWb, *attWh, *Wihh, *Whhh;
    float *s;
    cudaGetSymbolAddress((void**)&cur,    h_cur);
    cudaGetSymbolAddress((void**)&cur2,   h_cur2);
    cudaGetSymbolAddress((void**)&ctxpre, h_ctxpre);
    cudaGetSymbolAddress((void**)&ctx,    h_ctx);
    cudaGetSymbolAddress((void**)&apart,  h_apart);
    cudaGetSymbolAddress((void**)&s,      g_s);
    cudaGetSymbolAddress((void**)&atomh,  h_atom);
    cudaGetSymbolAddress((void**)&bondh,  h_bondl);
    cudaGetSymbolAddress((void**)&atomWh, h_atomW);
    cudaGetSymbolAddress((void**)&nbrWa,  h_nbrWa);
    cudaGetSymbolAddress((void**)&nbrWb,  h_nbrWb);
    cudaGetSymbolAddress((void**)&attWh,  h_attW);
    cudaGetSymbolAddress((void**)&Wihh,   h_Wih);
    cudaGetSymbolAddress((void**)&Whhh,   h_Whh);

    // 1. fused fp16 conversion of all GEMM operands
    w2h_all<<<ceil_div(W2H_C7, 256), 256>>>(
        atom_list, bond_list, atom_W, nbr_W, attend_W, gWih, gWhh,
        atomh, bondh, atomWh, nbrWa, nbrWb, attWh, Wihh, Whhh);

    // 2. cur = leaky(atom_list @ atom_W^T + atom_b)
    gemm_h<1, KPA><<<dim3(ceil_div(FF, SBN), MROWS / SBM), 256>>>(
        atomh, atomWh, atom_b, nullptr, cur, MROWS, FF);

    // 3. apart = atom_list @ Wa^T + nbr_b   (pre-activation, per-atom)
    gemm_h<0, KPA><<<dim3(ceil_div(FF, SBN), MROWS / SBM), 256>>>(
        atomh, nbrWa, nbr_b, nullptr, apart, MROWS, FF);

    // 4. bpart = bond_list @ Wb^T           (pre-activation, per-bond; bpart in h_ctx)
    gemm_h<0, KPB><<<dim3(ceil_div(FF, SBN), MROWS / SBM), 256>>>(
        bondh, nbrWb, nullptr, nullptr, ctx, MROWS, FF);

    __half* curbuf[2] = { cur, cur2 };
    for (int d = 0; d < RR; d++) {
        __half* curin   = curbuf[d & 1];
        __half* curoutp = curbuf[(d + 1) & 1];

        // round 0 gathers apart/bpart (bpart lives in ctx; read before ctx overwritten)
        attention_kernel<<<MROWS / 8, 256>>>(
            curin, apart, ctx, adeg, bdeg,
            align_W + (size_t)d * 2 * FF, align_b + d,
            ctxpre, s, (d == 0) ? 1 : 0);

        // context = elu(ctxpre @ attend_W^T + attend_b * s)
        gemm_h<2, KPF><<<dim3(ceil_div(FF, SBN), MROWS / SBM), 256>>>(
            ctxpre, attWh + (size_t)d * FF * FF, attend_b + (size_t)d * FF, s,
            ctx, MROWS, FF);

        gru_fused<<<dim3(13, MROWS / GBM), 256>>>(
            ctx, curin,
            Wihh + (size_t)d * 3 * FF * FF, Whhh + (size_t)d * 3 * FF * FF,
            gbih + (size_t)d * 3 * FF, gbhh + (size_t)d * 3 * FF,
            curoutp, out, (d == RR - 1) ? 1 : 0);
    }
}

// round 17
// speedup vs baseline: 1.4168x; 1.1622x over previous
#include <cuda_runtime.h>
#include <cuda_fp16.h>
#include <cstddef>

// Problem constants
#define BATCH 256
#define LSEQ  128
#define DD    6
#define FF    200
#define FA_   39
#define FB_   10
#define RR    2
#define MROWS (BATCH*LSEQ)          // 32768
#define KC    (FA_+FB_)             // 49
#define KPA   40                    // padded K for atom-side GEMMs
#define KPB   16                    // padded K for bond-side GEMM
#define KPF   200                   // F

// ---------------- scratch (device globals; no allocations allowed) ----------
__device__ __half h_cur   [(size_t)MROWS*FF];
__device__ __half h_cur2  [(size_t)MROWS*FF];
__device__ __half h_ctxpre[(size_t)MROWS*FF];
__device__ __half h_ctx   [(size_t)MROWS*FF];   // also bpart before round 0
__device__ __half h_apart [(size_t)MROWS*FF];
__device__ float  g_s     [MROWS];
__device__ __half h_atom  [(size_t)MROWS*KPA];
__device__ __half h_bondl [(size_t)MROWS*KPB];
__device__ __half h_atomW [FF*KPA];
__device__ __half h_nbrWa [FF*KPA];
__device__ __half h_nbrWb [FF*KPB];
__device__ __half h_attW  [RR*FF*FF];
__device__ __half h_Wih   [(size_t)RR*3*FF*FF];
__device__ __half h_Whh   [(size_t)RR*3*FF*FF];

// ---------------- PTX helpers ------------------------------------------------
__device__ __forceinline__ void mma_f16(float* c, const unsigned* a, const unsigned* b) {
    asm volatile(
        "mma.sync.aligned.m16n8k16.row.col.f32.f16.f16.f32 "
        "{%0,%1,%2,%3}, {%4,%5,%6,%7}, {%8,%9}, {%0,%1,%2,%3};"
        : "+f"(c[0]), "+f"(c[1]), "+f"(c[2]), "+f"(c[3])
        : "r"(a[0]), "r"(a[1]), "r"(a[2]), "r"(a[3]), "r"(b[0]), "r"(b[1]));
}

__device__ __forceinline__ void ldsm4(unsigned& r0, unsigned& r1, unsigned& r2, unsigned& r3,
                                      const void* p) {
    unsigned addr = (unsigned)__cvta_generic_to_shared(p);
    asm volatile("ldmatrix.sync.aligned.m8n8.x4.shared.b16 {%0,%1,%2,%3}, [%4];"
                 : "=r"(r0), "=r"(r1), "=r"(r2), "=r"(r3) : "r"(addr));
}

__device__ __forceinline__ void cpa16h(__half* dst, const __half* src, int bytes) {
    unsigned d = (unsigned)__cvta_generic_to_shared(dst);
    asm volatile("cp.async.cg.shared.global [%0], [%1], 16, %2;\n"
                 :: "r"(d), "l"(src), "r"(bytes));
}
__device__ __forceinline__ void cp_commit() { asm volatile("cp.async.commit_group;\n"); }
template<int N>
__device__ __forceinline__ void cp_wait() {
    asm volatile("cp.async.wait_group %0;\n" :: "n"(N));
}

// =================== fp16 tensor-core GEMM (BK=32, compile-time K) ==========
//   C[M,N] = act(A[M,KP] @ W[N,KP]^T + bias[N]*rowscale[M]), C stored __half.
//   ACT: 0=none, 1=leaky_relu(0.01), 2=elu.  bias may be null.
#define SBM 128
#define SBN 128
#define SBK 32
#define GSTG 3
#define EPS 136

template<int ACT, int KP>
__global__ void __launch_bounds__(256, 2)
gemm_h(const __half* __restrict__ A, const __half* __restrict__ W,
       const float* __restrict__ bias, const float* __restrict__ rowscale,
       __half* __restrict__ C, int M, int N)
{
    constexpr int NK = (KP + SBK - 1) / SBK;
    __shared__ __align__(16) __half smem_all[GSTG * (SBM + SBN) * SBK];
#define AS(S) ((__half(*)[SBK])(smem_all + (size_t)(S) * (SBM + SBN) * SBK))
#define BS(S) ((__half(*)[SBK])(smem_all + ((size_t)(S) * (SBM + SBN) + SBM) * SBK))

    const int tid   = threadIdx.x;
    const int lane  = tid & 31;
    const int warp  = tid >> 5;
    const int warpM = warp & 1;
    const int warpN = warp >> 1;
    const int mBase = blockIdx.y * SBM;
    const int nBase = blockIdx.x * SBN;
    const int r0 = lane >> 2;
    const int c0 = lane & 3;
    const int lrowA = ((lane >> 3) & 1) * 8 + (lane & 7);
    const int lchA  = lane >> 4;
    const int lrowB = (lane >> 4) * 8 + (lane & 7);
    const int lchB  = (lane >> 3) & 1;

    float acc[4][4][4];
    #pragma unroll
    for (int mt = 0; mt < 4; mt++)
        #pragma unroll
        for (int nt = 0; nt < 4; nt++)
            #pragma unroll
            for (int i = 0; i < 4; i++) acc[mt][nt][i] = 0.f;

#define LOAD(S, KT)                                                            \
    {                                                                          \
        const int kbase = (KT) * SBK;                                          \
        _Pragma("unroll")                                                      \
        for (int it = 0; it < 2; it++) {                                       \
            int e = tid + it * 256;                                            \
            int m = e >> 2, c = e & 3;                                         \
            int k0 = kbase + c * 8;                                            \
            int bytes = (k0 < KP) ? 16 : 0;                                    \
            const __half* src = A + (size_t)(mBase + m) * KP + (bytes ? k0 : 0);\
            cpa16h(&AS(S)[m][(c ^ ((m >> 1) & 3)) * 8], src, bytes);           \
        }                                                                      \
        _Pragma("unroll")                                                      \
        for (int it = 0; it < 2; it++) {                                       \
            int e = tid + it * 256;                                            \
            int n = e >> 2, c = e & 3;                                         \
            int gn = nBase + n, k0 = kbase + c * 8;                            \
            int bytes = (gn < N && k0 < KP) ? 16 : 0;                          \
            const __half* src = W + (size_t)(gn < N ? gn : 0) * KP             \
                                  + (bytes ? k0 : 0);                          \
            cpa16h(&BS(S)[n][(c ^ ((n >> 1) & 3)) * 8], src, bytes);           \
        }                                                                      \
        cp_commit();                                                           \
    }

    #pragma unroll
    for (int s = 0; s < GSTG - 1; s++) {
        if (s < NK) { LOAD(s, s); } else { cp_commit(); }
    }

    #pragma unroll
    for (int kt = 0; kt < NK; kt++) {
        const int st = kt % GSTG;
        cp_wait<GSTG - 2>();
        __syncthreads();

        if (kt + GSTG - 1 < NK) {
            LOAD((kt + GSTG - 1) % GSTG, kt + GSTG - 1);
        } else {
            cp_commit();
        }

        const __half (*as)[SBK] = AS(st);
        const __half (*bs)[SBK] = BS(st);

        #pragma unroll
        for (int hk = 0; hk < 2; hk++) {
            unsigned a[4][4];
            #pragma unroll
            for (int mt = 0; mt < 4; mt++) {
                int row = warpM * 64 + mt * 16 + lrowA;
                int ch = (hk * 2 + lchA) ^ ((row >> 1) & 3);
                ldsm4(a[mt][0], a[mt][1], a[mt][2], a[mt][3], &as[row][ch * 8]);
            }
            unsigned b[4][2];
            #pragma unroll
            for (int p = 0; p < 2; p++) {
                int row = warpN * 32 + p * 16 + lrowB;
                int ch = (hk * 2 + lchB) ^ ((row >> 1) & 3);
                unsigned t0, t1, t2, t3;
                ldsm4(t0, t1, t2, t3, &bs[row][ch * 8]);
                b[2 * p][0]     = t0; b[2 * p][1]     = t1;
                b[2 * p + 1][0] = t2; b[2 * p + 1][1] = t3;
            }
            #pragma unroll
            for (int mt = 0; mt < 4; mt++)
                #pragma unroll
                for (int nt = 0; nt < 4; nt++)
                    mma_f16(acc[mt][nt], a[mt], b[nt]);
        }
    }

    // -------- epilogue: bias+act -> padded smem -> coalesced STG.128 --------
    __syncthreads();
    __half* ep = smem_all;
    #pragma unroll
    for (int mt = 0; mt < 4; mt++) {
        int lr = warpM * 64 + mt * 16 + r0;
        int grow0 = mBase + lr;
        float s0 = rowscale ? rowscale[grow0]     : 1.f;
        float s1 = rowscale ? rowscale[grow0 + 8] : 1.f;
        #pragma unroll
        for (int nt = 0; nt < 4; nt++) {
            int lc  = warpN * 32 + nt * 8 + c0 * 2;
            int col = nBase + lc;
            float b0 = (bias && col < N)     ? bias[col]     : 0.f;
            float b1 = (bias && col + 1 < N) ? bias[col + 1] : 0.f;
            float v00 = acc[mt][nt][0] + b0 * s0;
            float v01 = acc[mt][nt][1] + b1 * s0;
            float v10 = acc[mt][nt][2] + b0 * s1;
            float v11 = acc[mt][nt][3] + b1 * s1;
            if (ACT == 1) {
                v00 = (v00 > 0.f) ? v00 : 0.01f * v00;
                v01 = (v01 > 0.f) ? v01 : 0.01f * v01;
                v10 = (v10 > 0.f) ? v10 : 0.01f * v10;
                v11 = (v11 > 0.f) ? v11 : 0.01f * v11;
            } else if (ACT == 2) {
                v00 = (v00 > 0.f) ? v00 : expm1f(v00);
                v01 = (v01 > 0.f) ? v01 : expm1f(v01);
                v10 = (v10 > 0.f) ? v10 : expm1f(v10);
                v11 = (v11 > 0.f) ? v11 : expm1f(v11);
            }
            *(half2*)&ep[(lr    ) * EPS + lc] = __floats2half2_rn(v00, v01);
            *(half2*)&ep[(lr + 8) * EPS + lc] = __floats2half2_rn(v10, v11);
        }
    }
    __syncthreads();
    for (int it = tid; it < SBM * 16; it += 256) {
        int r  = it >> 4, ck = it & 15;
        int gc = nBase + ck * 8;
        if (gc < N) {
            *(uint4*)&C[(size_t)(mBase + r) * N + gc] = *(const uint4*)&ep[r * EPS + ck * 8];
        }
    }
#undef LOAD
#undef AS
#undef BS
}

// =================== fused gi+gh GEMM + GRU epilogue (BK=32, dyn smem) =======
// Block: 128 rows x 16 F-cols; 6 gate tiles (Ncat=96), K=200, BK=32, NK=7.
// 8 warps (4M x 2N): warpN0 ctx@Wih, warpN1 cur@Whh. 3 stages x 22528B = 67.6KB
// dynamic smem; 2 blocks/SM (135KB).
#define GBM 128
#define GNC 96
#define FROWS (GBM + GBM + GNC)   // 352 rows/stage, 32 halves each
#define FSTG 3
#define GRU_SMEM (FSTG * FROWS * 32 * 2)   // 67584 B

__global__ void __launch_bounds__(256, 2)
gru_fused(const __half* __restrict__ ctx, const __half* __restrict__ cur,
          const __half* __restrict__ Wih, const __half* __restrict__ Whh,
          const float* __restrict__ bih, const float* __restrict__ bhh,
          __half* __restrict__ curout, float* __restrict__ outf, int finalr)
{
    extern __shared__ __align__(16) __half smraw[];
    constexpr int NK = (KPF + SBK - 1) / SBK;   // 7

    const int tid   = threadIdx.x;
    const int lane  = tid & 31;
    const int warp  = tid >> 5;
    const int warpM = warp & 3;
    const int warpN = warp >> 2;
    const int mBase = blockIdx.y * GBM;
    const int jBase = blockIdx.x * 16;
    const int r0 = lane >> 2;
    const int c0 = lane & 3;
    const int lrowA = ((lane >> 3) & 1) * 8 + (lane & 7);
    const int lchA  = lane >> 4;
    const int lrowB = (lane >> 4) * 8 + (lane & 7);
    const int lchB  = (lane >> 3) & 1;

    float acc[2][6][4];
    #pragma unroll
    for (int mt = 0; mt < 2; mt++)
        #pragma unroll
        for (int nt = 0; nt < 6; nt++)
            #pragma unroll
            for (int i = 0; i < 4; i++) acc[mt][nt][i] = 0.f;

#define SCTX(S) ((__half(*)[32])(smraw + (size_t)(S) * FROWS * 32))
#define SCUR(S) ((__half(*)[32])(smraw + ((size_t)(S) * FROWS + GBM) * 32))
#define SB(S)   ((__half(*)[32])(smraw + ((size_t)(S) * FROWS + 2*GBM) * 32))

#define FLOAD(S, KT)                                                           \
    {                                                                          \
        const int kbase = (KT) * SBK;                                          \
        _Pragma("unroll")                                                      \
        for (int it = 0; it < 2; it++) {                                       \
            int e = tid + it * 256;                                            \
            int m = e >> 2, c = e & 3;                                         \
            int k0 = kbase + c * 8;                                            \
            int bytes = (k0 < KPF) ? 16 : 0;                                   \
            size_t off = (size_t)(mBase + m) * KPF + (bytes ? k0 : 0);         \
            int sc = (c ^ ((m >> 1) & 3)) * 8;                                 \
            cpa16h(&SCTX(S)[m][sc], ctx + off, bytes);                         \
            cpa16h(&SCUR(S)[m][sc], cur + off, bytes);                         \
        }                                                                      \
        _Pragma("unroll")                                                      \
        for (int it = 0; it < 2; it++) {                                       \
            int e = tid + it * 256;                                            \
            if (e < 4 * GNC) {                                                 \
                int rn = e >> 2, c = e & 3;                                    \
                int gate = rn >> 4;                                            \
                int jj = jBase + (rn & 15);                                    \
                int k0 = kbase + c * 8;                                        \
                int bytes = (jj < FF && k0 < KPF) ? 16 : 0;                    \
                int jjc = (jj < FF) ? jj : 0;                                  \
                const __half* src = (gate < 3)                                 \
                    ? Wih + ((size_t)gate * FF + jjc) * KPF                    \
                    : Whh + ((size_t)(gate - 3) * FF + jjc) * KPF;             \
                cpa16h(&SB(S)[rn][(c ^ ((rn >> 1) & 3)) * 8],                  \
                       src + (bytes ? k0 : 0), bytes);                         \
            }                                                                  \
        }                                                                      \
        cp_commit();                                                           \
    }

    #pragma unroll
    for (int s = 0; s < FSTG - 1; s++) { FLOAD(s, s); }

    #pragma unroll
    for (int kt = 0; kt < NK; kt++) {
        const int st = kt % FSTG;
        cp_wait<FSTG - 2>();
        __syncthreads();

        if (kt + FSTG - 1 < NK) {
            FLOAD((kt + FSTG - 1) % FSTG, kt + FSTG - 1);
        } else {
            cp_commit();
        }

        const __half (*amat)[32] = warpN ? SCUR(st) : SCTX(st);
        const __half (*bs)[32]   = SB(st);

        #pragma unroll
        for (int hk = 0; hk < 2; hk++) {
            unsigned a[2][4];
            #pragma unroll
            for (int mt = 0; mt < 2; mt++) {
                int row = warpM * 32 + mt * 16 + lrowA;
                int ch = (hk * 2 + lchA) ^ ((row >> 1) & 3);
                ldsm4(a[mt][0], a[mt][1], a[mt][2], a[mt][3], &amat[row][ch * 8]);
            }
            unsigned b[6][2];
            #pragma unroll
            for (int p = 0; p < 3; p++) {
                int row = warpN * 48 + p * 16 + lrowB;
                int ch = (hk * 2 + lchB) ^ ((row >> 1) & 3);
                unsigned t0, t1, t2, t3;
                ldsm4(t0, t1, t2, t3, &bs[row][ch * 8]);
                b[2 * p][0]     = t0; b[2 * p][1]     = t1;
                b[2 * p + 1][0] = t2; b[2 * p + 1][1] = t3;
            }
            #pragma unroll
            for (int mt = 0; mt < 2; mt++)
                #pragma unroll
                for (int nt = 0; nt < 6; nt++)
                    mma_f16(acc[mt][nt], a[mt], b[nt]);
        }
    }

    // -------- exchange + GRU epilogue (paired half2/float2 stores) ----------
    __syncthreads();
    float* ex = (float*)smraw;          // 128 x 49 fp32 = 25088 B (fits 67.6KB)
    if (warpN == 1) {
        int base = (warpM * 32 + lane) * 49;
        #pragma unroll
        for (int mt = 0; mt < 2; mt++)
            #pragma unroll
            for (int nt = 0; nt < 6; nt++)
                #pragma unroll
                for (int i = 0; i < 4; i++)
                    ex[base + mt * 24 + nt * 4 + i] = acc[mt][nt][i];
    }
    __syncthreads();
    if (warpN == 0) {
        int base = (warpM * 32 + lane) * 49;
        #pragma unroll
        for (int mt = 0; mt < 2; mt++) {
            #pragma unroll
            for (int jh = 0; jh < 2; jh++) {
                int j0 = jBase + jh * 8 + c0 * 2;
                if (j0 < FF) {
                    #pragma unroll
                    for (int hf = 0; hf < 2; hf++) {
                        int row = mBase + warpM * 32 + mt * 16 + r0 + hf * 8;
                        half2 cpair = *(const half2*)&cur[(size_t)row * FF + j0];
                        float hv[2];
                        #pragma unroll
                        for (int q = 0; q < 2; q++) {
                            int i = hf * 2 + q;
                            int j = j0 + q;
                            float ir  = acc[mt][0 + jh][i] + bih[j];
                            float iz  = acc[mt][2 + jh][i] + bih[FF + j];
                            float inn = acc[mt][4 + jh][i] + bih[2 * FF + j];
                            float hr  = ex[base + mt * 24 + (0 + jh) * 4 + i] + bhh[j];
                            float hz  = ex[base + mt * 24 + (2 + jh) * 4 + i] + bhh[FF + j];
                            float hn  = ex[base + mt * 24 + (4 + jh) * 4 + i] + bhh[2 * FF + j];
                            float r = 1.f / (1.f + expf(-(ir + hr)));
                            float z = 1.f / (1.f + expf(-(iz + hz)));
                            float n = tanhf(inn + r * hn);
                            float c = q ? __half2float(__high2half(cpair))
                                        : __half2float(__low2half(cpair));
                            float h = (1.f - z) * n + z * c;
                            hv[q] = (h > 0.f) ? h : 0.f;
                        }
                        if (finalr) {
                            float2 t; t.x = hv[0]; t.y = hv[1];
                            *(float2*)&outf[(size_t)row * FF + j0] = t;
                        } else {
                            *(half2*)&curout[(size_t)row * FF + j0] =
                                __floats2half2_rn(hv[0], hv[1]);
                        }
                    }
                }
            }
        }
    }
#undef FLOAD
#undef SCTX
#undef SCUR
#undef SB
}

// ---------------- single fused fp32->fp16 (padded) conversion ---------------
#define W2H_C0 (MROWS*KPA)                 // atom_list
#define W2H_C1 (W2H_C0 + MROWS*KPB)        // bond_list
#define W2H_C2 (W2H_C1 + FF*KPA)           // atom_W
#define W2H_C3 (W2H_C2 + FF*KPA)           // nbr_W atom half
#define W2H_C4 (W2H_C3 + FF*KPB)           // nbr_W bond half
#define W2H_C5 (W2H_C4 + RR*FF*FF)         // attend_W
#define W2H_C6 (W2H_C5 + RR*3*FF*FF)       // gWih
#define W2H_C7 (W2H_C6 + RR*3*FF*FF)       // gWhh

__global__ void w2h_all(const float* __restrict__ atom_list,
                        const float* __restrict__ bond_list,
                        const float* __restrict__ atom_W,
                        const float* __restrict__ nbr_W,
                        const float* __restrict__ attend_W,
                        const float* __restrict__ gWih,
                        const float* __restrict__ gWhh,
                        __half* __restrict__ ha,   __half* __restrict__ hb,
                        __half* __restrict__ haw,
                        __half* __restrict__ hwa,  __half* __restrict__ hwb,
                        __half* __restrict__ hat,
                        __half* __restrict__ hwi,  __half* __restrict__ hwh)
{
    int i = blockIdx.x * blockDim.x + threadIdx.x;
    if (i < W2H_C0) {
        int n = i / KPA, k = i - n * KPA;
        ha[i] = (k < FA_) ? __float2half_rn(atom_list[(size_t)n * FA_ + k]) : __half(0.f);
    } else if (i < W2H_C1) {
        int j = i - W2H_C0; int n = j / KPB, k = j - n * KPB;
        hb[j] = (k < FB_) ? __float2half_rn(bond_list[(size_t)n * FB_ + k]) : __half(0.f);
    } else if (i < W2H_C2) {
        int j = i - W2H_C1; int n = j / KPA, k = j - n * KPA;
        haw[j] = (k < FA_) ? __float2half_rn(atom_W[(size_t)n * FA_ + k]) : __half(0.f);
    } else if (i < W2H_C3) {
        int j = i - W2H_C2; int n = j / KPA, k = j - n * KPA;
        hwa[j] = (k < FA_) ? __float2half_rn(nbr_W[(size_t)n * KC + k]) : __half(0.f);
    } else if (i < W2H_C4) {
        int j = i - W2H_C3; int n = j / KPB, k = j - n * KPB;
        hwb[j] = (k < FB_) ? __float2half_rn(nbr_W[(size_t)n * KC + FA_ + k]) : __half(0.f);
    } else if (i < W2H_C5) {
        int j = i - W2H_C4; hat[j] = __float2half_rn(attend_W[j]);
    } else if (i < W2H_C6) {
        int j = i - W2H_C5; hwi[j] = __float2half_rn(gWih[j]);
    } else if (i < W2H_C7) {
        int j = i - W2H_C6; hwh[j] = __float2half_rn(gWhh[j]);
    }
}

// ---------------- attention: warp per row ------------------------------------
// Round 0: nbr_feat[d] = leaky(apart[adeg] + bpart[bdeg])  (bias in apart)
// Round>0: nbr_feat[d] = cur[adeg]
__global__ void __launch_bounds__(256)
attention_kernel(const __half* __restrict__ cur,
                 const __half* __restrict__ apart,
                 const __half* __restrict__ bpart,
                 const int*    __restrict__ adeg,
                 const int*    __restrict__ bdeg,
                 const float*  __restrict__ alignW,
                 const float*  __restrict__ alignB,
                 __half* __restrict__ ctxpre,
                 float*  __restrict__ srow,
                 int first)
{
    int gw   = (blockIdx.x * blockDim.x + threadIdx.x) >> 5;
    int lane = threadIdx.x & 31;
    if (gw >= MROWS) return;
    const int r = gw;
    const int b = r >> 7;
    const float ab = alignB[0];

    float cv[7], a0[7], a1[7];
    #pragma unroll
    for (int i = 0; i < 7; i++) {
        int idx = lane + 32 * i;
        bool ok = idx < FF;
        cv[i] = ok ? __half2float(cur[(size_t)r * FF + idx]) : 0.f;
        a0[i] = ok ? alignW[idx]      : 0.f;
        a1[i] = ok ? alignW[FF + idx] : 0.f;
    }
    float qd = 0.f;
    #pragma unroll
    for (int i = 0; i < 7; i++) qd += cv[i] * a0[i];
    #pragma unroll
    for (int o = 16; o > 0; o >>= 1) qd += __shfl_xor_sync(0xffffffffu, qd, o);

    float nv[DD][7];
    float score[DD];
    int   nai[DD];

    #pragma unroll
    for (int d = 0; d < DD; d++) {
        int na = adeg[r * DD + d];
        nai[d] = na;
        float nd = 0.f;
        if (first) {
            int nb = bdeg[r * DD + d];
            const __half* ap = apart + (size_t)(b * LSEQ + na) * FF;
            const __half* bp = bpart + (size_t)(b * LSEQ + nb) * FF;
            #pragma unroll
            for (int i = 0; i < 7; i++) {
                int idx = lane + 32 * i;
                float v = 0.f;
                if (idx < FF) {
                    v = __half2float(ap[idx]) + __half2float(bp[idx]);
                    v = (v > 0.f) ? v : 0.01f * v;
                }
                nv[d][i] = v;
                nd += v * a1[i];
            }
        } else {
            const __half* np = cur + (size_t)(b * LSEQ + na) * FF;
            #pragma unroll
            for (int i = 0; i < 7; i++) {
                int idx = lane + 32 * i;
                float v = (idx < FF) ? __half2float(np[idx]) : 0.f;
                nv[d][i] = v;
                nd += v * a1[i];
            }
        }
        #pragma unroll
        for (int o = 16; o > 0; o >>= 1) nd += __shfl_xor_sync(0xffffffffu, nd, o);
        float sc = qd + nd + ab;
        sc = (sc > 0.f) ? sc : 0.01f * sc;
        if (na == LSEQ - 1) sc = sc - 9e8f;
        score[d] = sc;
    }

    float mx = score[0];
    #pragma unroll
    for (int d = 1; d < DD; d++) mx = fmaxf(mx, score[d]);
    float e[DD], den = 0.f;
    #pragma unroll
    for (int d = 0; d < DD; d++) { e[d] = expf(score[d] - mx); den += e[d]; }
    float inv = 1.f / den;
    float s = 0.f;
    #pragma unroll
    for (int d = 0; d < DD; d++) {
        float a = e[d] * inv;
        if (nai[d] == LSEQ - 1) a = 0.f;
        e[d] = a;
        s += a;
    }

    #pragma unroll
    for (int i = 0; i < 7; i++) {
        int idx = lane + 32 * i;
        if (idx < FF) {
            float v = 0.f;
            #pragma unroll
            for (int d = 0; d < DD; d++) v += e[d] * nv[d][i];
            ctxpre[(size_t)r * FF + idx] = __float2half_rn(v);
        }
    }
    if (lane == 0) srow[r] = s;
}

// ---------------- launch ------------------------------------------------------
static inline int ceil_div(int a, int b) { return (a + b - 1) / b; }

extern "C" void kernel_launch(void* const* d_in, const int* in_sizes, int n_in,
                              void* d_out, int out_size)
{
    const float* atom_list = (const float*)d_in[0];
    const float* bond_list = (const float*)d_in[1];
    const int*   adeg      = (const int*)  d_in[2];
    const int*   bdeg      = (const int*)  d_in[3];
    const float* atom_W    = (const float*)d_in[4];
    const float* atom_b    = (const float*)d_in[5];
    const float* nbr_W     = (const float*)d_in[6];
    const float* nbr_b     = (const float*)d_in[7];
    const float* align_W   = (const float*)d_in[8];
    const float* align_b   = (const float*)d_in[9];
    const float* attend_W  = (const float*)d_in[10];
    const float* attend_b  = (const float*)d_in[11];
    const float* gWih      = (const float*)d_in[12];
    const float* gWhh      = (const float*)d_in[13];
    const float* gbih      = (const float*)d_in[14];
    const float* gbhh      = (const float*)d_in[15];
    float* out = (float*)d_out;

    __half *cur, *cur2, *ctxpre, *ctx, *apart, *atomh, *bondh;
    __half *atomWh, *nbrWa, *nbrWb, *attWh, *Wihh, *Whhh;
    float *s;
    cudaGetSymbolAddress((void**)&cur,    h_cur);
    cudaGetSymbolAddress((void**)&cur2,   h_cur2);
    cudaGetSymbolAddress((void**)&ctxpre, h_ctxpre);
    cudaGetSymbolAddress((void**)&ctx,    h_ctx);
    cudaGetSymbolAddress((void**)&apart,  h_apart);
    cudaGetSymbolAddress((void**)&s,      g_s);
    cudaGetSymbolAddress((void**)&atomh,  h_atom);
    cudaGetSymbolAddress((void**)&bondh,  h_bondl);
    cudaGetSymbolAddress((void**)&atomWh, h_atomW);
    cudaGetSymbolAddress((void**)&nbrWa,  h_nbrWa);
    cudaGetSymbolAddress((void**)&nbrWb,  h_nbrWb);
    cudaGetSymbolAddress((void**)&attWh,  h_attW);
    cudaGetSymbolAddress((void**)&Wihh,   h_Wih);
    cudaGetSymbolAddress((void**)&Whhh,   h_Whh);

    // allow 67.6KB dynamic smem for gru_fused (idempotent, graph-capture-safe)
    cudaFuncSetAttribute(gru_fused, cudaFuncAttributeMaxDynamicSharedMemorySize,
                         GRU_SMEM);

    // 1. fused fp16 conversion of all GEMM operands
    w2h_all<<<ceil_div(W2H_C7, 256), 256>>>(
        atom_list, bond_list, atom_W, nbr_W, attend_W, gWih, gWhh,
        atomh, bondh, atomWh, nbrWa, nbrWb, attWh, Wihh, Whhh);

    // 2. cur = leaky(atom_list @ atom_W^T + atom_b)
    gemm_h<1, KPA><<<dim3(ceil_div(FF, SBN), MROWS / SBM), 256>>>(
        atomh, atomWh, atom_b, nullptr, cur, MROWS, FF);

    // 3. apart = atom_list @ Wa^T + nbr_b
    gemm_h<0, KPA><<<dim3(ceil_div(FF, SBN), MROWS / SBM), 256>>>(
        atomh, nbrWa, nbr_b, nullptr, apart, MROWS, FF);

    // 4. bpart = bond_list @ Wb^T   (bpart lives in h_ctx until round-0 attention)
    gemm_h<0, KPB><<<dim3(ceil_div(FF, SBN), MROWS / SBM), 256>>>(
        bondh, nbrWb, nullptr, nullptr, ctx, MROWS, FF);

    __half* curbuf[2] = { cur, cur2 };
    for (int d = 0; d < RR; d++) {
        __half* curin   = curbuf[d & 1];
        __half* curoutp = curbuf[(d + 1) & 1];

        attention_kernel<<<MROWS / 8, 256>>>(
            curin, apart, ctx, adeg, bdeg,
            align_W + (size_t)d * 2 * FF, align_b + d,
            ctxpre, s, (d == 0) ? 1 : 0);

        // context = elu(ctxpre @ attend_W^T + attend_b * s)
        gemm_h<2, KPF><<<dim3(ceil_div(FF, SBN), MROWS / SBM), 256>>>(
            ctxpre, attWh + (size_t)d * FF * FF, attend_b + (size_t)d * FF, s,
            ctx, MROWS, FF);

        gru_fused<<<dim3(13, MROWS / GBM), 256, GRU_SMEM>>>(
            ctx, curin,
            Wihh + (size_t)d * 3 * FF * FF, Whhh + (size_t)d * 3 * FF * FF,
            gbih + (size_t)d * 3 * FF, gbhh + (size_t)d * 3 * FF,
            curoutp, out, (d == RR - 1) ? 1 : 0);
    }
}